// round 15
// baseline (speedup 1.0000x reference)
#include <cuda_runtime.h>
#include <cuda_bf16.h>
#include <math.h>
#include <stdint.h>

#define NN 50000
#define NE 400000
#define NB 64
#define NTILE_E  3125
#define NTILE_N  782
#define NTILE_N2 391

// ---------------- device scratch ----------------
__device__ float g_sums[NN * 64];
__device__ int   g_cnt[NN];
__device__ float g_xw1[NN * 128];
__device__ __nv_bfloat16 g_a3h[NN * 256];
__device__ __nv_bfloat16 g_a3l[NN * 256];
__device__ __nv_bfloat16 g_a4h[NN * 128];
__device__ __nv_bfloat16 g_a4l[NN * 128];
__device__ __nv_bfloat16 g_xh[NN * 64];
__device__ __nv_bfloat16 g_xl[NN * 64];
__device__ __nv_bfloat16 g_uh[NB * 32];
__device__ __nv_bfloat16 g_ul[NB * 32];
__device__ int   g_flags[2];

// pre-split weight planes, laid out byte-identical to each kernel's smem layout
__device__ __align__(16) char g_w1ah[18432], g_w1al[18432];   // xw1 B  (stride 144)
__device__ __align__(16) char g_w1bh[18432], g_w1bl[18432];   // edge B1 (stride 144)
__device__ __align__(16) char g_w2h[17408],  g_w2l[17408];    // edge B2 (stride 272)
__device__ __align__(16) char g_w3h[86016],  g_w3l[86016];    // n1a B  (stride 336)
__device__ __align__(16) char g_w4h[67584],  g_w4l[67584];    // n1b B  (stride 528)
__device__ __align__(16) char g_wmh[17408],  g_wml[17408];    // n2 B   (stride 272)
__device__ __align__(16) char g_wxh[5120],   g_wxl[5120];     // n2 X   (stride 80)

// ---------------- helpers ----------------
__device__ __forceinline__ int ld_idx(const void* p, int i, int is64) {
    if (is64) return (int)((const long long*)p)[i];
    return ((const int*)p)[i];
}

__device__ __forceinline__ float jax_normal_eps(unsigned j) {
    const unsigned ks0 = 0u, ks1 = 42u;
    const unsigned ks2 = ks0 ^ ks1 ^ 0x1BD11BDAu;
    unsigned x0 = 0u + ks0;
    unsigned x1 = j + ks1;
#define TF_R(r) { x0 += x1; x1 = (x1 << (r)) | (x1 >> (32 - (r))); x1 ^= x0; }
    TF_R(13) TF_R(15) TF_R(26) TF_R(6)   x0 += ks1; x1 += ks2 + 1u;
    TF_R(17) TF_R(29) TF_R(16) TF_R(24)  x0 += ks2; x1 += ks0 + 2u;
    TF_R(13) TF_R(15) TF_R(26) TF_R(6)   x0 += ks0; x1 += ks1 + 3u;
    TF_R(17) TF_R(29) TF_R(16) TF_R(24)  x0 += ks1; x1 += ks2 + 4u;
    TF_R(13) TF_R(15) TF_R(26) TF_R(6)   x0 += ks2; x1 += ks0 + 5u;
#undef TF_R
    unsigned bits = x0 ^ x1;
    float u01 = __uint_as_float((bits >> 9) | 0x3F800000u) - 1.0f;
    const float lo = -0.99999994f;
    float uu = u01 * (1.0f - lo) + lo;
    uu = fmaxf(uu, lo);
    return 1.41421356237f * erfinvf(uu);
}

__device__ __forceinline__ uint32_t bfpack(float a, float b) {  // lo = a, hi = b
    uint32_t p;
    asm("cvt.rn.bf16x2.f32 %0, %1, %2;" : "=r"(p) : "f"(b), "f"(a));
    return p;
}
__device__ __forceinline__ float bflo_f(uint32_t p) { return __uint_as_float(p << 16); }
__device__ __forceinline__ float bfhi_f(uint32_t p) { return __uint_as_float(p & 0xffff0000u); }

__device__ __forceinline__ void mma_bf16(float* d, uint32_t a0, uint32_t a1,
                                         uint32_t a2, uint32_t a3,
                                         uint32_t b0, uint32_t b1) {
    asm volatile(
        "mma.sync.aligned.m16n8k16.row.col.f32.bf16.bf16.f32 "
        "{%0,%1,%2,%3}, {%4,%5,%6,%7}, {%8,%9}, {%0,%1,%2,%3};"
        : "+f"(d[0]), "+f"(d[1]), "+f"(d[2]), "+f"(d[3])
        : "r"(a0), "r"(a1), "r"(a2), "r"(a3), "r"(b0), "r"(b1));
}

__device__ __forceinline__ void ldmx4(uint32_t addr, uint32_t& r0, uint32_t& r1,
                                      uint32_t& r2, uint32_t& r3) {
    asm volatile("ldmatrix.sync.aligned.m8n8.x4.shared.b16 {%0,%1,%2,%3}, [%4];"
                 : "=r"(r0), "=r"(r1), "=r"(r2), "=r"(r3) : "r"(addr));
}

__device__ __forceinline__ uint32_t smem_u32(const void* p) {
    uint32_t a;
    asm("{ .reg .u64 t; cvta.to.shared.u64 t, %1; cvt.u32.u64 %0, t; }" : "=r"(a) : "l"(p));
    return a;
}

__device__ __forceinline__ uint32_t frag_off(int lane, int SB) {
    int lr = lane & 7, g = lane >> 3;
    return (uint32_t)((lr + (g & 1) * 8) * SB + (g >> 1) * 16);
}

#define BARG(id, cnt) asm volatile("bar.sync %0, %1;" :: "r"(id), "r"(cnt) : "memory")
#define CP16(dst, src) asm volatile("cp.async.cg.shared.global [%0], [%1], 16;" :: "r"(dst), "l"(src) : "memory")
#define CP_COMMIT() asm volatile("cp.async.commit_group;" ::: "memory")
#define CP_WAIT0() asm volatile("cp.async.wait_group 0;" ::: "memory")

// copy one hi/lo pair of pre-split planes gmem -> smem (linear, 16B chunks)
__device__ __forceinline__ void copy_planes(uint32_t dstH, uint32_t dstL,
                                            const char* srcH, const char* srcL,
                                            int bytes, int tid, int nthr) {
    int n16 = bytes >> 4;
    for (int i = tid; i < 2 * n16; i += nthr) {
        int pl = (i >= n16);
        int off = (i - (pl ? n16 : 0)) << 4;
        CP16((pl ? dstL : dstH) + off, (pl ? srcL : srcH) + off);
    }
}

#define MMA3_PAIR(ACC0, ACC1) \
    mma_bf16(ACC0, ah0, ah1, ah2, ah3, bh0, bh2); \
    mma_bf16(ACC1, ah0, ah1, ah2, ah3, bh1, bh3); \
    mma_bf16(ACC0, al0, al1, al2, al3, bh0, bh2); \
    mma_bf16(ACC1, al0, al1, al2, al3, bh1, bh3); \
    mma_bf16(ACC0, ah0, ah1, ah2, ah3, bl0, bl2); \
    mma_bf16(ACC1, ah0, ah1, ah2, ah3, bl1, bl3);

// ---------------- kernel: fused init (detect + zero + prep + weight split) ----------------
__global__ void k_init(const int* ei, const int* bt,
                       const float* __restrict__ x, const float* __restrict__ u,
                       const float* __restrict__ W1, const float* __restrict__ W2,
                       const float* __restrict__ W3, const float* __restrict__ W4,
                       const float* __restrict__ Wm, const float* __restrict__ Wv,
                       const float* __restrict__ Wx) {
    int i = blockIdx.x * blockDim.x + threadIdx.x;
    int stride = gridDim.x * blockDim.x;
    if (i == 0) {
        int e64 = 1;
        for (int j = 0; j < 64; j++)
            if (ei[2 * j + 1] != 0) { e64 = 0; break; }
        g_flags[0] = e64;
        int b64 = 1;
        int base = NN / 2;
        for (int j = 0; j < 64; j++)
            if (bt[base + 2 * j + 1] != 0) { b64 = 0; break; }
        g_flags[1] = b64;
    }
    for (int j = i; j < NN * 64; j += stride) g_sums[j] = 0.f;
    for (int j = i; j < NN; j += stride) g_cnt[j] = 0;
    const float4* x4 = (const float4*)x;
    for (int j = i; j < NN * 16; j += stride) {
        float4 v = x4[j];
        uint32_t p0 = bfpack(v.x, v.y), p1 = bfpack(v.z, v.w);
        uint32_t q0 = bfpack(v.x - bflo_f(p0), v.y - bfhi_f(p0));
        uint32_t q1 = bfpack(v.z - bflo_f(p1), v.w - bfhi_f(p1));
        *(uint2*)&g_xh[(size_t)j * 4] = make_uint2(p0, p1);
        *(uint2*)&g_xl[(size_t)j * 4] = make_uint2(q0, q1);
    }
    const float4* u4 = (const float4*)u;
    for (int j = i; j < NB * 8; j += stride) {
        float4 v = u4[j];
        uint32_t p0 = bfpack(v.x, v.y), p1 = bfpack(v.z, v.w);
        uint32_t q0 = bfpack(v.x - bflo_f(p0), v.y - bfhi_f(p0));
        uint32_t q1 = bfpack(v.z - bflo_f(p1), v.w - bfhi_f(p1));
        *(uint2*)&g_uh[j * 4] = make_uint2(p0, p1);
        *(uint2*)&g_ul[j * 4] = make_uint2(q0, q1);
    }
    // ---- weight hi/lo plane splits ----
    // xw1 B: W1 rows 0..63 ^T, stride 144
    for (int j = i; j < 128 * 32; j += stride) {
        int n = j & 127, k0 = (j >> 7) * 2;
        float w0 = W1[(size_t)k0 * 128 + n];
        float w1 = W1[(size_t)(k0 + 1) * 128 + n];
        uint32_t p = bfpack(w0, w1);
        uint32_t q = bfpack(w0 - bflo_f(p), w1 - bfhi_f(p));
        *(uint32_t*)(g_w1ah + n * 144 + k0 * 2) = p;
        *(uint32_t*)(g_w1al + n * 144 + k0 * 2) = q;
    }
    // edge B1: W1 rows 64..127 ^T, stride 144
    for (int j = i; j < 128 * 32; j += stride) {
        int n = j & 127, k0 = (j >> 7) * 2;
        float w0 = W1[(size_t)(64 + k0) * 128 + n];
        float w1 = W1[(size_t)(64 + k0 + 1) * 128 + n];
        uint32_t p = bfpack(w0, w1);
        uint32_t q = bfpack(w0 - bflo_f(p), w1 - bfhi_f(p));
        *(uint32_t*)(g_w1bh + n * 144 + k0 * 2) = p;
        *(uint32_t*)(g_w1bl + n * 144 + k0 * 2) = q;
    }
    // edge B2: W2^T, stride 272
    for (int j = i; j < 64 * 64; j += stride) {
        int n = j & 63, k0 = (j >> 6) * 2;
        float w0 = W2[(size_t)k0 * 64 + n];
        float w1 = W2[(size_t)(k0 + 1) * 64 + n];
        uint32_t p = bfpack(w0, w1);
        uint32_t q = bfpack(w0 - bflo_f(p), w1 - bfhi_f(p));
        *(uint32_t*)(g_w2h + n * 272 + k0 * 2) = p;
        *(uint32_t*)(g_w2l + n * 272 + k0 * 2) = q;
    }
    // n1a B: W3^T, stride 336
    for (int j = i; j < 256 * 80; j += stride) {
        int n = j & 255, k0 = (j >> 8) * 2;
        float w0 = W3[(size_t)k0 * 256 + n];
        float w1 = W3[(size_t)(k0 + 1) * 256 + n];
        uint32_t p = bfpack(w0, w1);
        uint32_t q = bfpack(w0 - bflo_f(p), w1 - bfhi_f(p));
        *(uint32_t*)(g_w3h + n * 336 + k0 * 2) = p;
        *(uint32_t*)(g_w3l + n * 336 + k0 * 2) = q;
    }
    // n1b B: W4^T, stride 528
    for (int j = i; j < 128 * 128; j += stride) {
        int n = j & 127, k0 = (j >> 7) * 2;
        float w0 = W4[(size_t)k0 * 128 + n];
        float w1 = W4[(size_t)(k0 + 1) * 128 + n];
        uint32_t p = bfpack(w0, w1);
        uint32_t q = bfpack(w0 - bflo_f(p), w1 - bfhi_f(p));
        *(uint32_t*)(g_w4h + n * 528 + k0 * 2) = p;
        *(uint32_t*)(g_w4l + n * 528 + k0 * 2) = q;
    }
    // n2 B: [Wm^T ; Wv^T], stride 272
    for (int j = i; j < 64 * 64; j += stride) {
        int n = j & 63, k0 = (j >> 6) * 2;
        float w0, w1;
        if (n < 32) { w0 = Wm[(size_t)k0 * 32 + n]; w1 = Wm[(size_t)(k0 + 1) * 32 + n]; }
        else        { w0 = Wv[(size_t)k0 * 32 + n - 32]; w1 = Wv[(size_t)(k0 + 1) * 32 + n - 32]; }
        uint32_t p = bfpack(w0, w1);
        uint32_t q = bfpack(w0 - bflo_f(p), w1 - bfhi_f(p));
        *(uint32_t*)(g_wmh + n * 272 + k0 * 2) = p;
        *(uint32_t*)(g_wml + n * 272 + k0 * 2) = q;
    }
    // n2 X: Wx^T, stride 80
    for (int j = i; j < 64 * 16; j += stride) {
        int n = j & 63, k0 = (j >> 6) * 2;
        float w0 = Wx[(size_t)k0 * 64 + n];
        float w1 = Wx[(size_t)(k0 + 1) * 64 + n];
        uint32_t p = bfpack(w0, w1);
        uint32_t q = bfpack(w0 - bflo_f(p), w1 - bfhi_f(p));
        *(uint32_t*)(g_wxh + n * 80 + k0 * 2) = p;
        *(uint32_t*)(g_wxl + n * 80 + k0 * 2) = q;
    }
}

// ================= kernel xw1: xw1 = x @ W1[0:64,:] =================
#define XW_SB 144
#define XW_BH 0
#define XW_BL 18432
#define XW_AH 36864
#define XW_AL 46080
#define SMEM_XW 55296

__global__ void __launch_bounds__(512, 1)
k_xw1() {
    extern __shared__ __align__(16) char smem[];
    const int tid = threadIdx.x;
    const int warp = tid >> 5, lane = tid & 31;
    const int tr = lane >> 2, tc = lane & 3;
    const int grp = warp >> 2, nh = warp & 3;
    const int m0 = grp * 16;
    const int gt = tid & 127;
    const int bid = 1 + grp;
    const uint32_t sbase = smem_u32(smem);
    const uint32_t fo = frag_off(lane, XW_SB);
    const uint32_t AhB = sbase + XW_AH, AlB = sbase + XW_AL;
    const uint32_t BhB = sbase + XW_BH, BlB = sbase + XW_BL;

    copy_planes(BhB, BlB, g_w1ah, g_w1al, 18432, tid, 512);
    CP_COMMIT();
    CP_WAIT0();
    __syncthreads();

    auto stage = [&](int n0) {
#pragma unroll
        for (int i = gt; i < 256; i += 128) {
            int plane = i >> 7, rem = i & 127;
            int rl = rem >> 3, c16 = rem & 7;
            int node = n0 + m0 + rl; if (node >= NN) node = NN - 1;
            const __nv_bfloat16* src = (plane ? g_xl : g_xh) + (size_t)node * 64 + c16 * 8;
            uint32_t dst = (plane ? AlB : AhB) + (uint32_t)(m0 + rl) * XW_SB + c16 * 16;
            CP16(dst, src);
        }
        CP_COMMIT();
    };

    int t = blockIdx.x;
    stage(t * 64);
    for (;;) {
        const int n0 = t * 64;
        CP_WAIT0();
        BARG(bid, 128);

        float acc[4][4];
#pragma unroll
        for (int nc = 0; nc < 4; nc++)
#pragma unroll
            for (int j = 0; j < 4; j++) acc[nc][j] = 0.f;
#pragma unroll
        for (int kc = 0; kc < 4; kc++) {
            const uint32_t kb = kc * 32;
            uint32_t ah0, ah1, ah2, ah3, al0, al1, al2, al3;
            ldmx4(AhB + m0 * XW_SB + fo + kb, ah0, ah1, ah2, ah3);
            ldmx4(AlB + m0 * XW_SB + fo + kb, al0, al1, al2, al3);
#pragma unroll
            for (int np = 0; np < 2; np++) {
                uint32_t bh0, bh1, bh2, bh3, bl0, bl1, bl2, bl3;
                uint32_t boff = (uint32_t)(nh * 32 + np * 16) * XW_SB + fo + kb;
                ldmx4(BhB + boff, bh0, bh1, bh2, bh3);
                ldmx4(BlB + boff, bl0, bl1, bl2, bl3);
                MMA3_PAIR(acc[2 * np], acc[2 * np + 1])
            }
        }
        BARG(bid, 128);

        const int tn = t + gridDim.x;
        const bool more = (tn < NTILE_N);
        if (more) stage(tn * 64);

        const int r0 = m0 + tr, r1 = r0 + 8;
        const int node0 = n0 + r0, node1 = n0 + r1;
#pragma unroll
        for (int nc = 0; nc < 4; nc++) {
            int col0 = nh * 32 + nc * 8 + 2 * tc;
            if (node0 < NN)
                *(float2*)&g_xw1[(size_t)node0 * 128 + col0] =
                    make_float2(acc[nc][0], acc[nc][1]);
            if (node1 < NN)
                *(float2*)&g_xw1[(size_t)node1 * 128 + col0] =
                    make_float2(acc[nc][2], acc[nc][3]);
        }
        if (!more) break;
        t = tn;
    }
}

// ================= kernel 2: edge MLP =================
#define E_SBA 144
#define E_SB2 272
#define EB1H  0
#define EB1L  18432
#define EB2H  36864
#define EB2L  54272
#define EAH   71680
#define EAL   90112
#define E2H   108544
#define E2L   143360
#define EB1S  178176
#define EG1S  178688
#define EBE1S 179200
#define EB2S  179712
#define EREDS 179968
#define EREDQ 180992
#define SMEM_EDGE 182016

__global__ void __launch_bounds__(512, 1)
k_edge_mma(const void* __restrict__ ei,
           const float* __restrict__ ea,
           const float* __restrict__ b1,
           const float* __restrict__ g1,
           const float* __restrict__ be1,
           const float* __restrict__ b2) {
    extern __shared__ __align__(16) char smem[];
    char* Aea = smem + EAH;
    char* Ael = smem + EAL;
    char* A2h = smem + E2H;
    char* A2l = smem + E2L;
    float* b1s  = (float*)(smem + EB1S);
    float* g1s  = (float*)(smem + EG1S);
    float* be1s = (float*)(smem + EBE1S);
    float* b2s  = (float*)(smem + EB2S);
    float* reds = (float*)(smem + EREDS);
    float* redq = (float*)(smem + EREDQ);

    const int tid = threadIdx.x;
    const int warp = tid >> 5, lane = tid & 31;
    const int tr = lane >> 2, tc = lane & 3;
    const int mq = warp >> 1, nhf = warp & 1;
    const int m0 = mq * 16;
    const int gt = tid & 63;
    const int bid = 1 + mq;
    const uint32_t sbase = smem_u32(smem);
    const uint32_t foA = frag_off(lane, E_SBA);
    const uint32_t fo2 = frag_off(lane, E_SB2);
    const uint32_t AeaB = sbase + EAH, AelB = sbase + EAL;
    const uint32_t A2hB = sbase + E2H, A2lB = sbase + E2L;
    const uint32_t B1hB = sbase + EB1H, B1lB = sbase + EB1L;
    const uint32_t B2hB = sbase + EB2H, B2lB = sbase + EB2L;

    if (tid < 128) { b1s[tid] = b1[tid]; g1s[tid] = g1[tid]; be1s[tid] = be1[tid]; }
    if (tid < 64)  b2s[tid] = b2[tid];
    copy_planes(B1hB, B1lB, g_w1bh, g_w1bl, 18432, tid, 512);
    copy_planes(B2hB, B2lB, g_w2h, g_w2l, 17408, tid, 512);
    CP_COMMIT();
    const int eflag = g_flags[0];
    CP_WAIT0();
    __syncthreads();

    auto stage_xw1 = [&](int e0) {
#pragma unroll
        for (int i = gt; i < 512; i += 64) {
            int el = i >> 5, seg = i & 31;
            int r = ld_idx(ei, e0 + m0 + el, eflag);
            const float* src = g_xw1 + (size_t)r * 128 + seg * 4;
            uint32_t dst = ((seg < 16) ? A2hB : A2lB)
                         + (uint32_t)(m0 + el) * E_SB2 + (uint32_t)(seg & 15) * 16;
            CP16(dst, src);
        }
        CP_COMMIT();
    };
    auto stage_ea = [&](int e0) {
        const float4* ea4 = (const float4*)(ea + (size_t)e0 * 64);
#pragma unroll
        for (int i = gt; i < 256; i += 64) {
            int el = i >> 4, cc = i & 15;
            float4 v = ea4[(size_t)(m0 + el) * 16 + cc];
            uint32_t p0 = bfpack(v.x, v.y), p1 = bfpack(v.z, v.w);
            uint32_t q0 = bfpack(v.x - bflo_f(p0), v.y - bfhi_f(p0));
            uint32_t q1 = bfpack(v.z - bflo_f(p1), v.w - bfhi_f(p1));
            *(uint2*)(Aea + (m0 + el) * E_SBA + cc * 8) = make_uint2(p0, p1);
            *(uint2*)(Ael + (m0 + el) * E_SBA + cc * 8) = make_uint2(q0, q1);
        }
    };

    int t = blockIdx.x;
    stage_xw1(t * 128);
    stage_ea(t * 128);

    for (;;) {
        const int e0 = t * 128;
        const int r0 = m0 + tr, r1 = r0 + 8;

        CP_WAIT0();
        BARG(bid, 64);

        const char* xwp = nhf ? A2l : A2h;
        float acc[8][4];
#pragma unroll
        for (int nc = 0; nc < 8; nc++) {
            int cb = (nc * 8 + 2 * tc) * 4;
            float2 v0 = *(const float2*)(xwp + r0 * E_SB2 + cb);
            float2 v1 = *(const float2*)(xwp + r1 * E_SB2 + cb);
            acc[nc][0] = v0.x; acc[nc][1] = v0.y;
            acc[nc][2] = v1.x; acc[nc][3] = v1.y;
        }

#pragma unroll
        for (int kc = 0; kc < 4; kc++) {
            const uint32_t kb = kc * 32;
            uint32_t ah0, ah1, ah2, ah3, al0, al1, al2, al3;
            ldmx4(AeaB + m0 * E_SBA + foA + kb, ah0, ah1, ah2, ah3);
            ldmx4(AelB + m0 * E_SBA + foA + kb, al0, al1, al2, al3);
#pragma unroll
            for (int np = 0; np < 4; np++) {
                uint32_t bh0, bh1, bh2, bh3, bl0, bl1, bl2, bl3;
                uint32_t boff = (uint32_t)(nhf * 64 + np * 16) * E_SBA + foA + kb;
                ldmx4(B1hB + boff, bh0, bh1, bh2, bh3);
                ldmx4(B1lB + boff, bl0, bl1, bl2, bl3);
                MMA3_PAIR(acc[2 * np], acc[2 * np + 1])
            }
        }

        float s0 = 0.f, q0s = 0.f, s1 = 0.f, q1s = 0.f;
#pragma unroll
        for (int nc = 0; nc < 8; nc++) {
            int col0 = nhf * 64 + nc * 8 + 2 * tc;
            float v0 = acc[nc][0] + b1s[col0];
            float v1 = acc[nc][1] + b1s[col0 + 1];
            float v2 = acc[nc][2] + b1s[col0];
            float v3 = acc[nc][3] + b1s[col0 + 1];
            acc[nc][0] = v0; acc[nc][1] = v1; acc[nc][2] = v2; acc[nc][3] = v3;
            s0 += v0 + v1; q0s = fmaf(v0, v0, fmaf(v1, v1, q0s));
            s1 += v2 + v3; q1s = fmaf(v2, v2, fmaf(v3, v3, q1s));
        }
#pragma unroll
        for (int o = 1; o <= 2; o <<= 1) {
            s0  += __shfl_xor_sync(0xffffffffu, s0, o);
            q0s += __shfl_xor_sync(0xffffffffu, q0s, o);
            s1  += __shfl_xor_sync(0xffffffffu, s1, o);
            q1s += __shfl_xor_sync(0xffffffffu, q1s, o);
        }
        if (tc == 0) {
            reds[nhf * 128 + r0] = s0; redq[nhf * 128 + r0] = q0s;
            reds[nhf * 128 + r1] = s1; redq[nhf * 128 + r1] = q1s;
        }
        BARG(bid, 64);
        float ts0 = reds[r0] + reds[128 + r0], tq0 = redq[r0] + redq[128 + r0];
        float ts1 = reds[r1] + reds[128 + r1], tq1 = redq[r1] + redq[128 + r1];
        float mean0 = ts0 * (1.f / 128.f);
        float rstd0 = rsqrtf(tq0 * (1.f / 128.f) - mean0 * mean0 + 1e-5f);
        float mean1 = ts1 * (1.f / 128.f);
        float rstd1 = rsqrtf(tq1 * (1.f / 128.f) - mean1 * mean1 + 1e-5f);
#pragma unroll
        for (int nc = 0; nc < 8; nc++) {
            int col0 = nhf * 64 + nc * 8 + 2 * tc;
            float w0 = fmaxf((acc[nc][0] - mean0) * rstd0 * g1s[col0]     + be1s[col0],     0.f);
            float w1 = fmaxf((acc[nc][1] - mean0) * rstd0 * g1s[col0 + 1] + be1s[col0 + 1], 0.f);
            float w2 = fmaxf((acc[nc][2] - mean1) * rstd1 * g1s[col0]     + be1s[col0],     0.f);
            float w3 = fmaxf((acc[nc][3] - mean1) * rstd1 * g1s[col0 + 1] + be1s[col0 + 1], 0.f);
            uint32_t p0 = bfpack(w0, w1);
            uint32_t q0 = bfpack(w0 - bflo_f(p0), w1 - bfhi_f(p0));
            uint32_t p1 = bfpack(w2, w3);
            uint32_t q1 = bfpack(w2 - bflo_f(p1), w3 - bfhi_f(p1));
            *(uint32_t*)(A2h + r0 * E_SB2 + col0 * 2) = p0;
            *(uint32_t*)(A2l + r0 * E_SB2 + col0 * 2) = q0;
            *(uint32_t*)(A2h + r1 * E_SB2 + col0 * 2) = p1;
            *(uint32_t*)(A2l + r1 * E_SB2 + col0 * 2) = q1;
        }
        BARG(bid, 64);

        float acc2[4][4];
#pragma unroll
        for (int nc = 0; nc < 4; nc++)
#pragma unroll
            for (int j = 0; j < 4; j++) acc2[nc][j] = 0.f;
#pragma unroll
        for (int kc = 0; kc < 8; kc++) {
            const uint32_t kb = kc * 32;
            uint32_t ah0, ah1, ah2, ah3, al0, al1, al2, al3;
            ldmx4(A2hB + m0 * E_SB2 + fo2 + kb, ah0, ah1, ah2, ah3);
            ldmx4(A2lB + m0 * E_SB2 + fo2 + kb, al0, al1, al2, al3);
#pragma unroll
            for (int np = 0; np < 2; np++) {
                uint32_t bh0, bh1, bh2, bh3, bl0, bl1, bl2, bl3;
                uint32_t boff = (uint32_t)(nhf * 32 + np * 16) * E_SB2 + fo2 + kb;
                ldmx4(B2hB + boff, bh0, bh1, bh2, bh3);
                ldmx4(B2lB + boff, bl0, bl1, bl2, bl3);
                MMA3_PAIR(acc2[2 * np], acc2[2 * np + 1])
            }
        }
        BARG(bid, 64);

        const int tn = t + gridDim.x;
        const bool more = (tn < NTILE_E);
        if (more) {
            stage_xw1(tn * 128);
            stage_ea(tn * 128);
        }

        const int c0 = ld_idx(ei, NE + e0 + r0, eflag);
        const int c1 = ld_idx(ei, NE + e0 + r1, eflag);
        float* d0 = g_sums + (size_t)c0 * 64;
        float* d1 = g_sums + (size_t)c1 * 64;
        const bool evn = (tc & 1) == 0;
#pragma unroll
        for (int nc = 0; nc < 4; nc++) {
            int col0 = nhf * 32 + nc * 8 + 2 * tc;
            float h0 = acc2[nc][0] + b2s[col0];
            float h1 = acc2[nc][1] + b2s[col0 + 1];
            float h2 = acc2[nc][2] + b2s[col0];
            float h3 = acc2[nc][3] + b2s[col0 + 1];
            float p0 = __shfl_xor_sync(0xffffffffu, h0, 1);
            float p1 = __shfl_xor_sync(0xffffffffu, h1, 1);
            float p2 = __shfl_xor_sync(0xffffffffu, h2, 1);
            float p3 = __shfl_xor_sync(0xffffffffu, h3, 1);
            int colv = nhf * 32 + nc * 8 + 4 * (tc >> 1);
            if (evn) {
                asm volatile("red.global.add.v4.f32 [%0], {%1, %2, %3, %4};"
                             :: "l"(d0 + colv), "f"(h0), "f"(h1), "f"(p0), "f"(p1) : "memory");
            } else {
                asm volatile("red.global.add.v4.f32 [%0], {%1, %2, %3, %4};"
                             :: "l"(d1 + colv), "f"(p2), "f"(p3), "f"(h2), "f"(h3) : "memory");
            }
        }
        if (nhf == 0 && tc == 0) {
            atomicAdd(&g_cnt[c0], 1);
            atomicAdd(&g_cnt[c1], 1);
        }
        if (!more) break;
        t = tn;
    }
}

// ================= kernel 3: n1a =================
#define N1A_SB   336
#define A3_B3H   0
#define A3_B3L   86016
#define A3_AH    172032
#define A3_AL    193536
#define A3_B3S   215040
#define A3_G3S   216064
#define A3_BE3S  217088
#define A3_REDS  218112
#define A3_REDQ  219136
#define SMEM_N1A 220160

__global__ void __launch_bounds__(512, 1)
k_n1a_mma(const void* bt,
          const float* __restrict__ b3,
          const float* __restrict__ g3,
          const float* __restrict__ be3) {
    extern __shared__ __align__(16) char smem[];
    char* Ah = smem + A3_AH;
    char* Al = smem + A3_AL;
    float* b3s  = (float*)(smem + A3_B3S);
    float* g3s  = (float*)(smem + A3_G3S);
    float* be3s = (float*)(smem + A3_BE3S);
    float* reds = (float*)(smem + A3_REDS);
    float* redq = (float*)(smem + A3_REDQ);

    const int tid = threadIdx.x;
    const int warp = tid >> 5, lane = tid & 31;
    const int tr = lane >> 2, tc = lane & 3;
    const int grp = warp >> 2, nh = warp & 3;
    const int m0 = grp * 16;
    const int gt = tid & 127;
    const int bid = 1 + grp;
    const uint32_t sbase = smem_u32(smem);
    const uint32_t fo = frag_off(lane, N1A_SB);
    const uint32_t AhB = sbase + A3_AH, AlB = sbase + A3_AL;
    const uint32_t BhB = sbase + A3_B3H, BlB = sbase + A3_B3L;

    if (tid < 256) { b3s[tid] = b3[tid]; g3s[tid] = g3[tid]; be3s[tid] = be3[tid]; }
    copy_planes(BhB, BlB, g_w3h, g_w3l, 86016, tid, 512);
    CP_COMMIT();
    const int bflag = g_flags[1];
    const float4* s4 = (const float4*)g_sums;
    CP_WAIT0();
    __syncthreads();

    auto stage = [&](int n0) {
#pragma unroll
        for (int i = gt; i < 256; i += 128) {
            int plane = i >> 7, rem = i & 127;
            int rl = rem >> 3, c16 = rem & 7;
            int node = n0 + m0 + rl; if (node >= NN) node = NN - 1;
            const __nv_bfloat16* src = (plane ? g_xl : g_xh) + (size_t)node * 64 + c16 * 8;
            uint32_t dst = (plane ? AlB : AhB) + (uint32_t)(m0 + rl) * N1A_SB + c16 * 16;
            CP16(dst, src);
        }
        {
            int plane = gt >> 6, rem = gt & 63;
            int rl = rem >> 2, c = rem & 3;
            int node = n0 + m0 + rl; if (node >= NN) node = NN - 1;
            int b = ld_idx(bt, node, bflag);
            const __nv_bfloat16* src = (plane ? g_ul : g_uh) + (size_t)b * 32 + c * 8;
            uint32_t dst = (plane ? AlB : AhB) + (uint32_t)(m0 + rl) * N1A_SB + 256 + c * 16;
            CP16(dst, src);
        }
        CP_COMMIT();
#pragma unroll
        for (int i = gt; i < 256; i += 128) {
            int rl = i >> 4, c4 = i & 15;
            int node = n0 + m0 + rl; if (node >= NN) node = NN - 1;
            float r = __frcp_rn(fmaxf((float)g_cnt[node], 1.f));
            float4 v = s4[(size_t)node * 16 + c4];
            v.x *= r; v.y *= r; v.z *= r; v.w *= r;
            uint32_t p0 = bfpack(v.x, v.y), p1 = bfpack(v.z, v.w);
            uint32_t q0 = bfpack(v.x - bflo_f(p0), v.y - bfhi_f(p0));
            uint32_t q1 = bfpack(v.z - bflo_f(p1), v.w - bfhi_f(p1));
            *(uint2*)(Ah + (m0 + rl) * N1A_SB + 128 + c4 * 8) = make_uint2(p0, p1);
            *(uint2*)(Al + (m0 + rl) * N1A_SB + 128 + c4 * 8) = make_uint2(q0, q1);
        }
    };

    int t = blockIdx.x;
    stage(t * 64);

    for (;;) {
        const int n0 = t * 64;
        CP_WAIT0();
        BARG(bid, 128);

        float acc[8][4];
#pragma unroll
        for (int nc = 0; nc < 8; nc++)
#pragma unroll
            for (int j = 0; j < 4; j++) acc[nc][j] = 0.f;
#pragma unroll
        for (int kc = 0; kc < 10; kc++) {
            const uint32_t kb = kc * 32;
            uint32_t ah0, ah1, ah2, ah3, al0, al1, al2, al3;
            ldmx4(AhB + m0 * N1A_SB + fo + kb, ah0, ah1, ah2, ah3);
            ldmx4(AlB + m0 * N1A_SB + fo + kb, al0, al1, al2, al3);
#pragma unroll
            for (int np = 0; np < 4; np++) {
                uint32_t bh0, bh1, bh2, bh3, bl0, bl1, bl2, bl3;
                uint32_t boff = (uint32_t)(nh * 64 + np * 16) * N1A_SB + fo + kb;
                ldmx4(BhB + boff, bh0, bh1, bh2, bh3);
                ldmx4(BlB + boff, bl0, bl1, bl2, bl3);
                MMA3_PAIR(acc[2 * np], acc[2 * np + 1])
            }
        }

        float s0 = 0.f, q0s = 0.f, s1 = 0.f, q1s = 0.f;
#pragma unroll
        for (int nc = 0; nc < 8; nc++) {
            int col0 = nh * 64 + nc * 8 + 2 * tc;
            float v0 = acc[nc][0] + b3s[col0];
            float v1 = acc[nc][1] + b3s[col0 + 1];
            float v2 = acc[nc][2] + b3s[col0];
            float v3 = acc[nc][3] + b3s[col0 + 1];
            acc[nc][0] = v0; acc[nc][1] = v1; acc[nc][2] = v2; acc[nc][3] = v3;
            s0 += v0 + v1; q0s = fmaf(v0, v0, fmaf(v1, v1, q0s));
            s1 += v2 + v3; q1s = fmaf(v2, v2, fmaf(v3, v3, q1s));
        }
#pragma unroll
        for (int o = 1; o <= 2; o <<= 1) {
            s0  += __shfl_xor_sync(0xffffffffu, s0, o);
            q0s += __shfl_xor_sync(0xffffffffu, q0s, o);
            s1  += __shfl_xor_sync(0xffffffffu, s1, o);
            q1s += __shfl_xor_sync(0xffffffffu, q1s, o);
        }
        const int r0 = m0 + tr, r1 = r0 + 8;
        if (tc == 0) {
            reds[nh * 64 + r0] = s0; redq[nh * 64 + r0] = q0s;
            reds[nh * 64 + r1] = s1; redq[nh * 64 + r1] = q1s;
        }
        BARG(bid, 128);

        const int tn = t + gridDim.x;
        const bool more = (tn < NTILE_N);
        if (more) stage(tn * 64);

        float ts0 = reds[r0] + reds[64 + r0] + reds[128 + r0] + reds[192 + r0];
        float tq0 = redq[r0] + redq[64 + r0] + redq[128 + r0] + redq[192 + r0];
        float ts1 = reds[r1] + reds[64 + r1] + reds[128 + r1] + reds[192 + r1];
        float tq1 = redq[r1] + redq[64 + r1] + redq[128 + r1] + redq[192 + r1];
        float mean0 = ts0 * (1.f / 256.f);
        float rstd0 = rsqrtf(tq0 * (1.f / 256.f) - mean0 * mean0 + 1e-5f);
        float mean1 = ts1 * (1.f / 256.f);
        float rstd1 = rsqrtf(tq1 * (1.f / 256.f) - mean1 * mean1 + 1e-5f);

        const int node0 = n0 + r0, node1 = n0 + r1;
#pragma unroll
        for (int nc = 0; nc < 8; nc++) {
            int col0 = nh * 64 + nc * 8 + 2 * tc;
            float w0 = fmaxf((acc[nc][0] - mean0) * rstd0 * g3s[col0]     + be3s[col0],     0.f);
            float w1 = fmaxf((acc[nc][1] - mean0) * rstd0 * g3s[col0 + 1] + be3s[col0 + 1], 0.f);
            float w2 = fmaxf((acc[nc][2] - mean1) * rstd1 * g3s[col0]     + be3s[col0],     0.f);
            float w3 = fmaxf((acc[nc][3] - mean1) * rstd1 * g3s[col0 + 1] + be3s[col0 + 1], 0.f);
            if (node0 < NN) {
                uint32_t p = bfpack(w0, w1);
                uint32_t q = bfpack(w0 - bflo_f(p), w1 - bfhi_f(p));
                *(uint32_t*)&g_a3h[(size_t)node0 * 256 + col0] = p;
                *(uint32_t*)&g_a3l[(size_t)node0 * 256 + col0] = q;
            }
            if (node1 < NN) {
                uint32_t p = bfpack(w2, w3);
                uint32_t q = bfpack(w2 - bflo_f(p), w3 - bfhi_f(p));
                *(uint32_t*)&g_a3h[(size_t)node1 * 256 + col0] = p;
                *(uint32_t*)&g_a3l[(size_t)node1 * 256 + col0] = q;
            }
        }
        if (!more) break;
        t = tn;
    }
}

// ================= kernel 4: n1b =================
#define N1B_SB   528
#define A4_B4H   0
#define A4_B4L   67584
#define A4_AH    135168
#define A4_AL    168960
#define A4_B4S   202752
#define A4_G4S   203264
#define A4_BE4S  203776
#define A4_REDS  204288
#define A4_REDQ  205312
#define SMEM_N1B 206336

__global__ void __launch_bounds__(512, 1)
k_n1b_mma(const float* __restrict__ b4,
          const float* __restrict__ g4,
          const float* __restrict__ be4) {
    extern __shared__ __align__(16) char smem[];
    float* b4s  = (float*)(smem + A4_B4S);
    float* g4s  = (float*)(smem + A4_G4S);
    float* be4s = (float*)(smem + A4_BE4S);
    float* reds = (float*)(smem + A4_REDS);
    float* redq = (float*)(smem + A4_REDQ);

    const int tid = threadIdx.x;
    const int warp = tid >> 5, lane = tid & 31;
    const int tr = lane >> 2, tc = lane & 3;
    const int grp = warp >> 2, nh = warp & 3;
    const int m0 = grp * 16;
    const int gt = tid & 127;
    const int bid = 1 + grp;
    const uint32_t sbase = smem_u32(smem);
    const uint32_t fo = frag_off(lane, N1B_SB);
    const uint32_t AhB = sbase + A4_AH, AlB = sbase + A4_AL;
    const uint32_t BhB = sbase + A4_B4H, BlB = sbase + A4_B4L;

    if (tid < 128) { b4s[tid] = b4[tid]; g4s[tid] = g4[tid]; be4s[tid] = be4[tid]; }
    copy_planes(BhB, BlB, g_w4h, g_w4l, 67584, tid, 512);
    CP_COMMIT();
    CP_WAIT0();
    __syncthreads();

    auto stage = [&](int n0) {
#pragma unroll
        for (int i = gt; i < 1024; i += 128) {
            int plane = i >> 9, rem = i & 511;
            int rl = rem >> 5, c16 = rem & 31;
            int node = n0 + m0 + rl; if (node >= NN) node = NN - 1;
            const __nv_bfloat16* src = (plane ? g_a3l : g_a3h) + (size_t)node * 256 + c16 * 8;
            uint32_t dst = (plane ? AlB : AhB) + (uint32_t)(m0 + rl) * N1B_SB + c16 * 16;
            CP16(dst, src);
        }
        CP_COMMIT();
    };

    int t = blockIdx.x;
    stage(t * 64);

    for (;;) {
        const int n0 = t * 64;
        CP_WAIT0();
        BARG(bid, 128);

        float acc[4][4];
#pragma unroll
        for (int nc = 0; nc < 4; nc++)
#pragma unroll
            for (int j = 0; j < 4; j++) acc[nc][j] = 0.f;
#pragma unroll
        for (int kc = 0; kc < 16; kc++) {
            const uint32_t kb = kc * 32;
            uint32_t ah0, ah1, ah2, ah3, al0, al1, al2, al3;
            ldmx4(AhB + m0 * N1B_SB + fo + kb, ah0, ah1, ah2, ah3);
            ldmx4(AlB + m0 * N1B_SB + fo + kb, al0, al1, al2, al3);
#pragma unroll
            for (int np = 0; np < 2; np++) {
                uint32_t bh0, bh1, bh2, bh3, bl0, bl1, bl2, bl3;
                uint32_t boff = (uint32_t)(nh * 32 + np * 16) * N1B_SB + fo + kb;
                ldmx4(BhB + boff, bh0, bh1, bh2, bh3);
                ldmx4(BlB + boff, bl0, bl1, bl2, bl3);
                MMA3_PAIR(acc[2 * np], acc[2 * np + 1])
            }
        }

        float s0 = 0.f, q0s = 0.f, s1 = 0.f, q1s = 0.f;
#pragma unroll
        for (int nc = 0; nc < 4; nc++) {
            int col0 = nh * 32 + nc * 8 + 2 * tc;
            float v0 = acc[nc][0] + b4s[col0];
            float v1 = acc[nc][1] + b4s[col0 + 1];
            float v2 = acc[nc][2] + b4s[col0];
            float v3 = acc[nc][3] + b4s[col0 + 1];
            acc[nc][0] = v0; acc[nc][1] = v1; acc[nc][2] = v2; acc[nc][3] = v3;
            s0 += v0 + v1; q0s = fmaf(v0, v0, fmaf(v1, v1, q0s));
            s1 += v2 + v3; q1s = fmaf(v2, v2, fmaf(v3, v3, q1s));
        }
#pragma unroll
        for (int o = 1; o <= 2; o <<= 1) {
            s0  += __shfl_xor_sync(0xffffffffu, s0, o);
            q0s += __shfl_xor_sync(0xffffffffu, q0s, o);
            s1  += __shfl_xor_sync(0xffffffffu, s1, o);
            q1s += __shfl_xor_sync(0xffffffffu, q1s, o);
        }
        const int r0 = m0 + tr, r1 = r0 + 8;
        if (tc == 0) {
            reds[nh * 64 + r0] = s0; redq[nh * 64 + r0] = q0s;
            reds[nh * 64 + r1] = s1; redq[nh * 64 + r1] = q1s;
        }
        BARG(bid, 128);

        const int tn = t + gridDim.x;
        const bool more = (tn < NTILE_N);
        if (more) stage(tn * 64);

        float ts0 = reds[r0] + reds[64 + r0] + reds[128 + r0] + reds[192 + r0];
        float tq0 = redq[r0] + redq[64 + r0] + redq[128 + r0] + redq[192 + r0];
        float ts1 = reds[r1] + reds[64 + r1] + reds[128 + r1] + reds[192 + r1];
        float tq1 = redq[r1] + redq[64 + r1] + redq[128 + r1] + redq[192 + r1];
        float mean0 = ts0 * (1.f / 128.f);
        float rstd0 = rsqrtf(tq0 * (1.f / 128.f) - mean0 * mean0 + 1e-5f);
        float mean1 = ts1 * (1.f / 128.f);
        float rstd1 = rsqrtf(tq1 * (1.f / 128.f) - mean1 * mean1 + 1e-5f);

        const int node0 = n0 + r0, node1 = n0 + r1;
#pragma unroll
        for (int nc = 0; nc < 4; nc++) {
            int col0 = nh * 32 + nc * 8 + 2 * tc;
            float w0 = fmaxf((acc[nc][0] - mean0) * rstd0 * g4s[col0]     + be4s[col0],     0.f);
            float w1 = fmaxf((acc[nc][1] - mean0) * rstd0 * g4s[col0 + 1] + be4s[col0 + 1], 0.f);
            float w2 = fmaxf((acc[nc][2] - mean1) * rstd1 * g4s[col0]     + be4s[col0],     0.f);
            float w3 = fmaxf((acc[nc][3] - mean1) * rstd1 * g4s[col0 + 1] + be4s[col0 + 1], 0.f);
            if (node0 < NN) {
                uint32_t p = bfpack(w0, w1);
                uint32_t q = bfpack(w0 - bflo_f(p), w1 - bfhi_f(p));
                *(uint32_t*)&g_a4h[(size_t)node0 * 128 + col0] = p;
                *(uint32_t*)&g_a4l[(size_t)node0 * 128 + col0] = q;
            }
            if (node1 < NN) {
                uint32_t p = bfpack(w2, w3);
                uint32_t q = bfpack(w2 - bflo_f(p), w3 - bfhi_f(p));
                *(uint32_t*)&g_a4h[(size_t)node1 * 128 + col0] = p;
                *(uint32_t*)&g_a4l[(size_t)node1 * 128 + col0] = q;
            }
        }
        if (!more) break;
        t = tn;
    }
}

// ================= kernel 5: n2 =================
#define N2_SB    272
#define Z_SB     80
#define N2_BH    0
#define N2_BL    17408
#define N2_AH    34816
#define N2_AL    69632
#define N2_ZH    104448
#define N2_ZL    114688
#define N2_XH    124928
#define N2_XL    130048
#define N2_MUV   135168
#define N2_BM    169984
#define N2_BV    170112
#define N2_BX    170240
#define SMEM_N2  170496

__global__ void __launch_bounds__(512, 1)
k_n2_mma(const float* __restrict__ bm,
         const float* __restrict__ bv,
         const float* __restrict__ bx,
         float* __restrict__ out) {
    extern __shared__ __align__(16) char smem[];
    char* Zh = smem + N2_ZH;
    char* Zl = smem + N2_ZL;
    float* muv = (float*)(smem + N2_MUV);
    float* bms = (float*)(smem + N2_BM);
    float* bvs = (float*)(smem + N2_BV);
    float* bxs = (float*)(smem + N2_BX);

    const int tid = threadIdx.x;
    const int warp = tid >> 5, lane = tid & 31;
    const int tr = lane >> 2, tc = lane & 3;
    const int mq = warp >> 1, nhf = warp & 1;
    const int m0 = mq * 16;
    const int gt = tid & 63;
    const int bid = 1 + mq;
    const uint32_t sbase = smem_u32(smem);
    const uint32_t foA = frag_off(lane, N2_SB);
    const uint32_t foZ = frag_off(lane, Z_SB);
    const uint32_t AhB = sbase + N2_AH, AlB = sbase + N2_AL;
    const uint32_t BhB = sbase + N2_BH, BlB = sbase + N2_BL;
    const uint32_t ZhB = sbase + N2_ZH, ZlB = sbase + N2_ZL;
    const uint32_t XhB = sbase + N2_XH, XlB = sbase + N2_XL;

    if (tid < 32) { bms[tid] = bm[tid]; bvs[tid] = bv[tid]; }
    if (tid < 64) bxs[tid] = bx[tid];
    copy_planes(BhB, BlB, g_wmh, g_wml, 17408, tid, 512);
    copy_planes(XhB, XlB, g_wxh, g_wxl, 5120, tid, 512);
    CP_COMMIT();
    CP_WAIT0();
    __syncthreads();

    auto stage = [&](int n0) {
#pragma unroll
        for (int i = gt; i < 512; i += 64) {
            int plane = i >> 8, rem = i & 255;
            int rl = rem >> 4, c16 = rem & 15;
            int node = n0 + m0 + rl; if (node >= NN) node = NN - 1;
            const __nv_bfloat16* src = (plane ? g_a4l : g_a4h) + (size_t)node * 128 + c16 * 8;
            uint32_t dst = (plane ? AlB : AhB) + (uint32_t)(m0 + rl) * N2_SB + c16 * 16;
            CP16(dst, src);
        }
        CP_COMMIT();
    };

    int t = blockIdx.x;
    stage(t * 128);

    for (;;) {
        const int n0 = t * 128;
        CP_WAIT0();
        BARG(bid, 64);

        float acc[4][4];
#pragma unroll
        for (int nc = 0; nc < 4; nc++)
#pragma unroll
            for (int j = 0; j < 4; j++) acc[nc][j] = 0.f;
#pragma unroll
        for (int kc = 0; kc < 8; kc++) {
            const uint32_t kb = kc * 32;
            uint32_t ah0, ah1, ah2, ah3, al0, al1, al2, al3;
            ldmx4(AhB + m0 * N2_SB + foA + kb, ah0, ah1, ah2, ah3);
            ldmx4(AlB + m0 * N2_SB + foA + kb, al0, al1, al2, al3);
#pragma unroll
            for (int np = 0; np < 2; np++) {
                uint32_t bh0, bh1, bh2, bh3, bl0, bl1, bl2, bl3;
                uint32_t boff = (uint32_t)(nhf * 32 + np * 16) * N2_SB + foA + kb;
                ldmx4(BhB + boff, bh0, bh1, bh2, bh3);
                ldmx4(BlB + boff, bl0, bl1, bl2, bl3);
                MMA3_PAIR(acc[2 * np], acc[2 * np + 1])
            }
        }

        const int r0 = m0 + tr, r1 = r0 + 8;
#pragma unroll
        for (int nc = 0; nc < 4; nc++) {
            int col0 = nhf * 32 + nc * 8 + 2 * tc;
            float bb0 = (nhf == 0) ? bms[col0]     : bvs[col0 - 32];
            float bb1 = (nhf == 0) ? bms[col0 + 1] : bvs[col0 - 31];
            int so = (nhf == 0) ? col0 : col0 + 2;
            muv[r0 * 68 + so]     = acc[nc][0] + bb0;
            muv[r0 * 68 + so + 1] = acc[nc][1] + bb1;
            muv[r1 * 68 + so]     = acc[nc][2] + bb0;
            muv[r1 * 68 + so + 1] = acc[nc][3] + bb1;
        }
        BARG(bid, 64);

        const int tn = t + gridDim.x;
        const bool more = (tn < NTILE_N2);
        if (more) stage(tn * 128);

#pragma unroll
        for (int it = 0; it < 8; it++) {
            int idx = it * 64 + gt;
            int rl = idx >> 5, col = idx & 31;
            int row = m0 + rl, node = n0 + row;
            float mu = muv[row * 68 + col];
            float lv = muv[row * 68 + 34 + col];
            float z = mu + jax_normal_eps((unsigned)(node * 32 + col)) * expf(0.5f * lv);
            __nv_bfloat16 zh = __float2bfloat16_rn(z);
            *(__nv_bfloat16*)(Zh + row * Z_SB + col * 2) = zh;
            *(__nv_bfloat16*)(Zl + row * Z_SB + col * 2) =
                __float2bfloat16_rn(z - __bfloat162float(zh));
            if (node < NN) {
                out[(size_t)NN * 64 + (size_t)node * 32 + col] = mu;
                out[(size_t)NN * 96 + (size_t)node * 32 + col] = lv;
            }
        }
        BARG(bid, 64);

        float acc2[4][4];
#pragma unroll
        for (int nc = 0; nc < 4; nc++)
#pragma unroll
            for (int j = 0; j < 4; j++) acc2[nc][j] = 0.f;
#pragma unroll
        for (int kc = 0; kc < 2; kc++) {
            const uint32_t kb = kc * 32;
            uint32_t ah0, ah1, ah2, ah3, al0, al1, al2, al3;
            ldmx4(ZhB + m0 * Z_SB + foZ + kb, ah0, ah1, ah2, ah3);
            ldmx4(ZlB + m0 * Z_SB + foZ + kb, al0, al1, al2, al3);
#pragma unroll
            for (int np = 0; np < 2; np++) {
                uint32_t bh0, bh1, bh2, bh3, bl0, bl1, bl2, bl3;
                uint32_t boff = (uint32_t)(nhf * 32 + np * 16) * Z_SB + foZ + kb;
                ldmx4(XhB + boff, bh0, bh1, bh2, bh3);
                ldmx4(XlB + boff, bl0, bl1, bl2, bl3);
                MMA3_PAIR(acc2[2 * np], acc2[2 * np + 1])
            }
        }
        const int node0 = n0 + r0, node1 = n0 + r1;
#pragma unroll
        for (int nc = 0; nc < 4; nc++) {
            int col0 = nhf * 32 + nc * 8 + 2 * tc;
            if (node0 < NN)
                *(float2*)&out[(size_t)node0 * 64 + col0] =
                    make_float2(acc2[nc][0] + bxs[col0], acc2[nc][1] + bxs[col0 + 1]);
            if (node1 < NN)
                *(float2*)&out[(size_t)node1 * 64 + col0] =
                    make_float2(acc2[nc][2] + bxs[col0], acc2[nc][3] + bxs[col0 + 1]);
        }
        if (!more) break;
        t = tn;
    }
}

// ---------------- launch ----------------
extern "C" void kernel_launch(void* const* d_in, const int* in_sizes, int n_in,
                              void* d_out, int out_size) {
    const float* x  = (const float*)d_in[0];
    const void*  ei = d_in[1];
    const float* ea = (const float*)d_in[2];
    const float* u  = (const float*)d_in[3];
    const void*  bt = d_in[4];
    const float* W1 = (const float*)d_in[6];  const float* b1  = (const float*)d_in[7];
    const float* g1 = (const float*)d_in[8];  const float* be1 = (const float*)d_in[9];
    const float* W2 = (const float*)d_in[10]; const float* b2  = (const float*)d_in[11];
    const float* W3 = (const float*)d_in[12]; const float* b3  = (const float*)d_in[13];
    const float* g3 = (const float*)d_in[14]; const float* be3 = (const float*)d_in[15];
    const float* W4 = (const float*)d_in[16]; const float* b4  = (const float*)d_in[17];
    const float* g4 = (const float*)d_in[18]; const float* be4 = (const float*)d_in[19];
    const float* Wm = (const float*)d_in[20]; const float* bm  = (const float*)d_in[21];
    const float* Wv = (const float*)d_in[22]; const float* bv  = (const float*)d_in[23];
    const float* Wx = (const float*)d_in[24]; const float* bx  = (const float*)d_in[25];
    float* out = (float*)d_out;

    cudaFuncSetAttribute(k_xw1, cudaFuncAttributeMaxDynamicSharedMemorySize, SMEM_XW);
    cudaFuncSetAttribute(k_edge_mma, cudaFuncAttributeMaxDynamicSharedMemorySize, SMEM_EDGE);
    cudaFuncSetAttribute(k_n1a_mma, cudaFuncAttributeMaxDynamicSharedMemorySize, SMEM_N1A);
    cudaFuncSetAttribute(k_n1b_mma, cudaFuncAttributeMaxDynamicSharedMemorySize, SMEM_N1B);
    cudaFuncSetAttribute(k_n2_mma,  cudaFuncAttributeMaxDynamicSharedMemorySize, SMEM_N2);

    k_init<<<256, 256>>>((const int*)ei, (const int*)bt, x, u, W1, W2, W3, W4, Wm, Wv, Wx);
    k_xw1<<<148, 512, SMEM_XW>>>();
    k_edge_mma<<<148, 512, SMEM_EDGE>>>(ei, ea, b1, g1, be1, b2);
    k_n1a_mma<<<148, 512, SMEM_N1A>>>(bt, b3, g3, be3);
    k_n1b_mma<<<148, 512, SMEM_N1B>>>(b4, g4, be4);
    k_n2_mma<<<148, 512, SMEM_N2>>>(bm, bv, bx, out);
}

// round 17
// speedup vs baseline: 1.4392x; 1.4392x over previous
#include <cuda_runtime.h>
#include <cuda_bf16.h>
#include <math.h>
#include <stdint.h>

#define NN 50000
#define NE 400000
#define NB 64
#define NTILE_E  3125
#define NTILE_N  782
#define NTILE_N2 391

// ---------------- device scratch ----------------
__device__ float g_sums[NN * 64];
__device__ int   g_cnt[NN];
__device__ float g_xw1[NN * 128];
__device__ __nv_bfloat16 g_a3h[NN * 256];
__device__ __nv_bfloat16 g_a3l[NN * 256];
__device__ __nv_bfloat16 g_a4h[NN * 128];
__device__ __nv_bfloat16 g_a4l[NN * 128];
__device__ __nv_bfloat16 g_xh[NN * 64];
__device__ __nv_bfloat16 g_xl[NN * 64];
__device__ __nv_bfloat16 g_uh[NB * 32];
__device__ __nv_bfloat16 g_ul[NB * 32];
__device__ int   g_flags[2];

// ---------------- helpers ----------------
__device__ __forceinline__ int ld_idx(const void* p, int i, int is64) {
    if (is64) return (int)((const long long*)p)[i];
    return ((const int*)p)[i];
}

__device__ __forceinline__ float jax_normal_eps(unsigned j) {
    const unsigned ks0 = 0u, ks1 = 42u;
    const unsigned ks2 = ks0 ^ ks1 ^ 0x1BD11BDAu;
    unsigned x0 = 0u + ks0;
    unsigned x1 = j + ks1;
#define TF_R(r) { x0 += x1; x1 = (x1 << (r)) | (x1 >> (32 - (r))); x1 ^= x0; }
    TF_R(13) TF_R(15) TF_R(26) TF_R(6)   x0 += ks1; x1 += ks2 + 1u;
    TF_R(17) TF_R(29) TF_R(16) TF_R(24)  x0 += ks2; x1 += ks0 + 2u;
    TF_R(13) TF_R(15) TF_R(26) TF_R(6)   x0 += ks0; x1 += ks1 + 3u;
    TF_R(17) TF_R(29) TF_R(16) TF_R(24)  x0 += ks1; x1 += ks2 + 4u;
    TF_R(13) TF_R(15) TF_R(26) TF_R(6)   x0 += ks2; x1 += ks0 + 5u;
#undef TF_R
    unsigned bits = x0 ^ x1;
    float u01 = __uint_as_float((bits >> 9) | 0x3F800000u) - 1.0f;
    const float lo = -0.99999994f;
    float uu = u01 * (1.0f - lo) + lo;
    uu = fmaxf(uu, lo);
    return 1.41421356237f * erfinvf(uu);
}

__device__ __forceinline__ uint32_t bfpack(float a, float b) {  // lo = a, hi = b
    uint32_t p;
    asm("cvt.rn.bf16x2.f32 %0, %1, %2;" : "=r"(p) : "f"(b), "f"(a));
    return p;
}
__device__ __forceinline__ float bflo_f(uint32_t p) { return __uint_as_float(p << 16); }
__device__ __forceinline__ float bfhi_f(uint32_t p) { return __uint_as_float(p & 0xffff0000u); }

__device__ __forceinline__ void mma_bf16(float* d, uint32_t a0, uint32_t a1,
                                         uint32_t a2, uint32_t a3,
                                         uint32_t b0, uint32_t b1) {
    asm volatile(
        "mma.sync.aligned.m16n8k16.row.col.f32.bf16.bf16.f32 "
        "{%0,%1,%2,%3}, {%4,%5,%6,%7}, {%8,%9}, {%0,%1,%2,%3};"
        : "+f"(d[0]), "+f"(d[1]), "+f"(d[2]), "+f"(d[3])
        : "r"(a0), "r"(a1), "r"(a2), "r"(a3), "r"(b0), "r"(b1));
}

__device__ __forceinline__ void ldmx4(uint32_t addr, uint32_t& r0, uint32_t& r1,
                                      uint32_t& r2, uint32_t& r3) {
    asm volatile("ldmatrix.sync.aligned.m8n8.x4.shared.b16 {%0,%1,%2,%3}, [%4];"
                 : "=r"(r0), "=r"(r1), "=r"(r2), "=r"(r3) : "r"(addr));
}

__device__ __forceinline__ uint32_t smem_u32(const void* p) {
    uint32_t a;
    asm("{ .reg .u64 t; cvta.to.shared.u64 t, %1; cvt.u32.u64 %0, t; }" : "=r"(a) : "l"(p));
    return a;
}

__device__ __forceinline__ uint32_t frag_off(int lane, int SB) {
    int lr = lane & 7, g = lane >> 3;
    return (uint32_t)((lr + (g & 1) * 8) * SB + (g >> 1) * 16);
}

#define BARG(id, cnt) asm volatile("bar.sync %0, %1;" :: "r"(id), "r"(cnt) : "memory")
#define CP16(dst, src) asm volatile("cp.async.cg.shared.global [%0], [%1], 16;" :: "r"(dst), "l"(src) : "memory")
#define CP_COMMIT() asm volatile("cp.async.commit_group;" ::: "memory")
#define CP_WAIT0() asm volatile("cp.async.wait_group 0;" ::: "memory")

#define MMA3_PAIR(ACC0, ACC1) \
    mma_bf16(ACC0, ah0, ah1, ah2, ah3, bh0, bh2); \
    mma_bf16(ACC1, ah0, ah1, ah2, ah3, bh1, bh3); \
    mma_bf16(ACC0, al0, al1, al2, al3, bh0, bh2); \
    mma_bf16(ACC1, al0, al1, al2, al3, bh1, bh3); \
    mma_bf16(ACC0, ah0, ah1, ah2, ah3, bl0, bl2); \
    mma_bf16(ACC1, ah0, ah1, ah2, ah3, bl1, bl3);

// ---------------- kernel: fused init (detect + zero + prep) ----------------
__global__ void k_init(const int* ei, const int* bt,
                       const float* __restrict__ x, const float* __restrict__ u) {
    int i = blockIdx.x * blockDim.x + threadIdx.x;
    int stride = gridDim.x * blockDim.x;
    if (i == 0) {
        int e64 = 1;
        for (int j = 0; j < 64; j++)
            if (ei[2 * j + 1] != 0) { e64 = 0; break; }
        g_flags[0] = e64;
        int b64 = 1;
        int base = NN / 2;
        for (int j = 0; j < 64; j++)
            if (bt[base + 2 * j + 1] != 0) { b64 = 0; break; }
        g_flags[1] = b64;
    }
    for (int j = i; j < NN * 64; j += stride) g_sums[j] = 0.f;
    for (int j = i; j < NN; j += stride) g_cnt[j] = 0;
    const float4* x4 = (const float4*)x;
    for (int j = i; j < NN * 16; j += stride) {
        float4 v = x4[j];
        uint32_t p0 = bfpack(v.x, v.y), p1 = bfpack(v.z, v.w);
        uint32_t q0 = bfpack(v.x - bflo_f(p0), v.y - bfhi_f(p0));
        uint32_t q1 = bfpack(v.z - bflo_f(p1), v.w - bfhi_f(p1));
        *(uint2*)&g_xh[(size_t)j * 4] = make_uint2(p0, p1);
        *(uint2*)&g_xl[(size_t)j * 4] = make_uint2(q0, q1);
    }
    const float4* u4 = (const float4*)u;
    for (int j = i; j < NB * 8; j += stride) {
        float4 v = u4[j];
        uint32_t p0 = bfpack(v.x, v.y), p1 = bfpack(v.z, v.w);
        uint32_t q0 = bfpack(v.x - bflo_f(p0), v.y - bfhi_f(p0));
        uint32_t q1 = bfpack(v.z - bflo_f(p1), v.w - bfhi_f(p1));
        *(uint2*)&g_uh[j * 4] = make_uint2(p0, p1);
        *(uint2*)&g_ul[j * 4] = make_uint2(q0, q1);
    }
}

// ================= kernel xw1: xw1 = x @ W1[0:64,:] =================
#define XW_SB 144
#define XW_BH 0
#define XW_BL 18432
#define XW_AH 36864
#define XW_AL 46080
#define SMEM_XW 55296

__global__ void __launch_bounds__(512, 1)
k_xw1(const float* __restrict__ W1) {
    extern __shared__ __align__(16) char smem[];
    char* Bh = smem + XW_BH;
    char* Bl = smem + XW_BL;
    const int tid = threadIdx.x;
    const int warp = tid >> 5, lane = tid & 31;
    const int tr = lane >> 2, tc = lane & 3;
    const int grp = warp >> 2, nh = warp & 3;
    const int m0 = grp * 16;
    const int gt = tid & 127;
    const int bid = 1 + grp;
    const uint32_t sbase = smem_u32(smem);
    const uint32_t fo = frag_off(lane, XW_SB);
    const uint32_t AhB = sbase + XW_AH, AlB = sbase + XW_AL;
    const uint32_t BhB = sbase + XW_BH, BlB = sbase + XW_BL;

    for (int i = tid; i < 128 * 32; i += 512) {
        int n = i & 127, k0 = (i >> 7) * 2;
        float w0 = W1[(size_t)k0 * 128 + n];
        float w1 = W1[(size_t)(k0 + 1) * 128 + n];
        uint32_t p = bfpack(w0, w1);
        uint32_t q = bfpack(w0 - bflo_f(p), w1 - bfhi_f(p));
        *(uint32_t*)(Bh + n * XW_SB + k0 * 2) = p;
        *(uint32_t*)(Bl + n * XW_SB + k0 * 2) = q;
    }
    __syncthreads();

    auto stage = [&](int n0) {
#pragma unroll
        for (int i = gt; i < 256; i += 128) {
            int plane = i >> 7, rem = i & 127;
            int rl = rem >> 3, c16 = rem & 7;
            int node = n0 + m0 + rl; if (node >= NN) node = NN - 1;
            const __nv_bfloat16* src = (plane ? g_xl : g_xh) + (size_t)node * 64 + c16 * 8;
            uint32_t dst = (plane ? AlB : AhB) + (uint32_t)(m0 + rl) * XW_SB + c16 * 16;
            CP16(dst, src);
        }
        CP_COMMIT();
    };

    int t = blockIdx.x;
    stage(t * 64);
    for (;;) {
        const int n0 = t * 64;
        CP_WAIT0();
        BARG(bid, 128);

        float acc[4][4];
#pragma unroll
        for (int nc = 0; nc < 4; nc++)
#pragma unroll
            for (int j = 0; j < 4; j++) acc[nc][j] = 0.f;
#pragma unroll
        for (int kc = 0; kc < 4; kc++) {
            const uint32_t kb = kc * 32;
            uint32_t ah0, ah1, ah2, ah3, al0, al1, al2, al3;
            ldmx4(AhB + m0 * XW_SB + fo + kb, ah0, ah1, ah2, ah3);
            ldmx4(AlB + m0 * XW_SB + fo + kb, al0, al1, al2, al3);
#pragma unroll
            for (int np = 0; np < 2; np++) {
                uint32_t bh0, bh1, bh2, bh3, bl0, bl1, bl2, bl3;
                uint32_t boff = (uint32_t)(nh * 32 + np * 16) * XW_SB + fo + kb;
                ldmx4(BhB + boff, bh0, bh1, bh2, bh3);
                ldmx4(BlB + boff, bl0, bl1, bl2, bl3);
                MMA3_PAIR(acc[2 * np], acc[2 * np + 1])
            }
        }
        BARG(bid, 128);

        const int tn = t + gridDim.x;
        const bool more = (tn < NTILE_N);
        if (more) stage(tn * 64);

        const int r0 = m0 + tr, r1 = r0 + 8;
        const int node0 = n0 + r0, node1 = n0 + r1;
#pragma unroll
        for (int nc = 0; nc < 4; nc++) {
            int col0 = nh * 32 + nc * 8 + 2 * tc;
            if (node0 < NN)
                *(float2*)&g_xw1[(size_t)node0 * 128 + col0] =
                    make_float2(acc[nc][0], acc[nc][1]);
            if (node1 < NN)
                *(float2*)&g_xw1[(size_t)node1 * 128 + col0] =
                    make_float2(acc[nc][2], acc[nc][3]);
        }
        if (!more) break;
        t = tn;
    }
}

// ================= kernel 2: edge MLP =================
#define E_SBA 144
#define E_SB2 272
#define EB1H  0
#define EB1L  18432
#define EB2H  36864
#define EB2L  54272
#define EAH   71680
#define EAL   90112
#define E2H   108544
#define E2L   143360
#define EB1S  178176
#define EG1S  178688
#define EBE1S 179200
#define EB2S  179712
#define EREDS 179968
#define EREDQ 180992
#define SMEM_EDGE 182016

__global__ void __launch_bounds__(512, 1)
k_edge_mma(const void* __restrict__ ei,
           const float* __restrict__ ea,
           const float* __restrict__ W1,
           const float* __restrict__ b1,
           const float* __restrict__ g1,
           const float* __restrict__ be1,
           const float* __restrict__ W2,
           const float* __restrict__ b2) {
    extern __shared__ __align__(16) char smem[];
    __nv_bfloat16* B2h = (__nv_bfloat16*)(smem + EB2H);
    __nv_bfloat16* B2l = (__nv_bfloat16*)(smem + EB2L);
    char* Bh1 = smem + EB1H;
    char* Bl1 = smem + EB1L;
    char* Aea = smem + EAH;
    char* Ael = smem + EAL;
    char* A2h = smem + E2H;
    char* A2l = smem + E2L;
    float* b1s  = (float*)(smem + EB1S);
    float* g1s  = (float*)(smem + EG1S);
    float* be1s = (float*)(smem + EBE1S);
    float* b2s  = (float*)(smem + EB2S);
    float* reds = (float*)(smem + EREDS);
    float* redq = (float*)(smem + EREDQ);

    const int tid = threadIdx.x;
    const int warp = tid >> 5, lane = tid & 31;
    const int tr = lane >> 2, tc = lane & 3;
    const int mq = warp >> 1, nhf = warp & 1;
    const int m0 = mq * 16;
    const int gt = tid & 63;
    const int bid = 1 + mq;
    const uint32_t sbase = smem_u32(smem);
    const uint32_t foA = frag_off(lane, E_SBA);
    const uint32_t fo2 = frag_off(lane, E_SB2);
    const uint32_t AeaB = sbase + EAH, AelB = sbase + EAL;
    const uint32_t A2hB = sbase + E2H, A2lB = sbase + E2L;
    const uint32_t B1hB = sbase + EB1H, B1lB = sbase + EB1L;
    const uint32_t B2hB = sbase + EB2H, B2lB = sbase + EB2L;

    if (tid < 128) { b1s[tid] = b1[tid]; g1s[tid] = g1[tid]; be1s[tid] = be1[tid]; }
    if (tid < 64)  b2s[tid] = b2[tid];
    for (int i = tid; i < 128 * 32; i += 512) {
        int n = i & 127, k0 = (i >> 7) * 2;
        float w0 = W1[(size_t)(64 + k0) * 128 + n];
        float w1 = W1[(size_t)(64 + k0 + 1) * 128 + n];
        uint32_t p = bfpack(w0, w1);
        uint32_t q = bfpack(w0 - bflo_f(p), w1 - bfhi_f(p));
        *(uint32_t*)(Bh1 + n * E_SBA + k0 * 2) = p;
        *(uint32_t*)(Bl1 + n * E_SBA + k0 * 2) = q;
    }
    for (int i = tid; i < 64 * 64; i += 512) {
        int n = i & 63, k0 = (i >> 6) * 2;
        float w0 = W2[(size_t)k0 * 64 + n];
        float w1 = W2[(size_t)(k0 + 1) * 64 + n];
        uint32_t p = bfpack(w0, w1);
        uint32_t q = bfpack(w0 - bflo_f(p), w1 - bfhi_f(p));
        *(uint32_t*)((char*)B2h + n * 272 + k0 * 2) = p;
        *(uint32_t*)((char*)B2l + n * 272 + k0 * 2) = q;
    }
    const int eflag = g_flags[0];
    __syncthreads();

    auto stage_xw1 = [&](int e0) {
#pragma unroll
        for (int i = gt; i < 512; i += 64) {
            int el = i >> 5, seg = i & 31;
            int r = ld_idx(ei, e0 + m0 + el, eflag);
            const float* src = g_xw1 + (size_t)r * 128 + seg * 4;
            uint32_t dst = ((seg < 16) ? A2hB : A2lB)
                         + (uint32_t)(m0 + el) * E_SB2 + (uint32_t)(seg & 15) * 16;
            CP16(dst, src);
        }
        CP_COMMIT();
    };
    auto stage_ea = [&](int e0) {
        const float4* ea4 = (const float4*)(ea + (size_t)e0 * 64);
#pragma unroll
        for (int i = gt; i < 256; i += 64) {
            int el = i >> 4, cc = i & 15;
            float4 v = ea4[(size_t)(m0 + el) * 16 + cc];
            uint32_t p0 = bfpack(v.x, v.y), p1 = bfpack(v.z, v.w);
            uint32_t q0 = bfpack(v.x - bflo_f(p0), v.y - bfhi_f(p0));
            uint32_t q1 = bfpack(v.z - bflo_f(p1), v.w - bfhi_f(p1));
            *(uint2*)(Aea + (m0 + el) * E_SBA + cc * 8) = make_uint2(p0, p1);
            *(uint2*)(Ael + (m0 + el) * E_SBA + cc * 8) = make_uint2(q0, q1);
        }
    };

    int t = blockIdx.x;
    stage_xw1(t * 128);
    stage_ea(t * 128);

    for (;;) {
        const int e0 = t * 128;
        const int r0 = m0 + tr, r1 = r0 + 8;

        CP_WAIT0();
        BARG(bid, 64);

        const char* xwp = nhf ? A2l : A2h;
        float acc[8][4];
#pragma unroll
        for (int nc = 0; nc < 8; nc++) {
            int cb = (nc * 8 + 2 * tc) * 4;
            float2 v0 = *(const float2*)(xwp + r0 * E_SB2 + cb);
            float2 v1 = *(const float2*)(xwp + r1 * E_SB2 + cb);
            acc[nc][0] = v0.x; acc[nc][1] = v0.y;
            acc[nc][2] = v1.x; acc[nc][3] = v1.y;
        }

#pragma unroll
        for (int kc = 0; kc < 4; kc++) {
            const uint32_t kb = kc * 32;
            uint32_t ah0, ah1, ah2, ah3, al0, al1, al2, al3;
            ldmx4(AeaB + m0 * E_SBA + foA + kb, ah0, ah1, ah2, ah3);
            ldmx4(AelB + m0 * E_SBA + foA + kb, al0, al1, al2, al3);
#pragma unroll
            for (int np = 0; np < 4; np++) {
                uint32_t bh0, bh1, bh2, bh3, bl0, bl1, bl2, bl3;
                uint32_t boff = (uint32_t)(nhf * 64 + np * 16) * E_SBA + foA + kb;
                ldmx4(B1hB + boff, bh0, bh1, bh2, bh3);
                ldmx4(B1lB + boff, bl0, bl1, bl2, bl3);
                MMA3_PAIR(acc[2 * np], acc[2 * np + 1])
            }
        }

        float s0 = 0.f, q0s = 0.f, s1 = 0.f, q1s = 0.f;
#pragma unroll
        for (int nc = 0; nc < 8; nc++) {
            int col0 = nhf * 64 + nc * 8 + 2 * tc;
            float v0 = acc[nc][0] + b1s[col0];
            float v1 = acc[nc][1] + b1s[col0 + 1];
            float v2 = acc[nc][2] + b1s[col0];
            float v3 = acc[nc][3] + b1s[col0 + 1];
            acc[nc][0] = v0; acc[nc][1] = v1; acc[nc][2] = v2; acc[nc][3] = v3;
            s0 += v0 + v1; q0s = fmaf(v0, v0, fmaf(v1, v1, q0s));
            s1 += v2 + v3; q1s = fmaf(v2, v2, fmaf(v3, v3, q1s));
        }
#pragma unroll
        for (int o = 1; o <= 2; o <<= 1) {
            s0  += __shfl_xor_sync(0xffffffffu, s0, o);
            q0s += __shfl_xor_sync(0xffffffffu, q0s, o);
            s1  += __shfl_xor_sync(0xffffffffu, s1, o);
            q1s += __shfl_xor_sync(0xffffffffu, q1s, o);
        }
        if (tc == 0) {
            reds[nhf * 128 + r0] = s0; redq[nhf * 128 + r0] = q0s;
            reds[nhf * 128 + r1] = s1; redq[nhf * 128 + r1] = q1s;
        }
        BARG(bid, 64);
        float ts0 = reds[r0] + reds[128 + r0], tq0 = redq[r0] + redq[128 + r0];
        float ts1 = reds[r1] + reds[128 + r1], tq1 = redq[r1] + redq[128 + r1];
        float mean0 = ts0 * (1.f / 128.f);
        float rstd0 = rsqrtf(tq0 * (1.f / 128.f) - mean0 * mean0 + 1e-5f);
        float mean1 = ts1 * (1.f / 128.f);
        float rstd1 = rsqrtf(tq1 * (1.f / 128.f) - mean1 * mean1 + 1e-5f);
#pragma unroll
        for (int nc = 0; nc < 8; nc++) {
            int col0 = nhf * 64 + nc * 8 + 2 * tc;
            float w0 = fmaxf((acc[nc][0] - mean0) * rstd0 * g1s[col0]     + be1s[col0],     0.f);
            float w1 = fmaxf((acc[nc][1] - mean0) * rstd0 * g1s[col0 + 1] + be1s[col0 + 1], 0.f);
            float w2 = fmaxf((acc[nc][2] - mean1) * rstd1 * g1s[col0]     + be1s[col0],     0.f);
            float w3 = fmaxf((acc[nc][3] - mean1) * rstd1 * g1s[col0 + 1] + be1s[col0 + 1], 0.f);
            uint32_t p0 = bfpack(w0, w1);
            uint32_t q0 = bfpack(w0 - bflo_f(p0), w1 - bfhi_f(p0));
            uint32_t p1 = bfpack(w2, w3);
            uint32_t q1 = bfpack(w2 - bflo_f(p1), w3 - bfhi_f(p1));
            *(uint32_t*)(A2h + r0 * E_SB2 + col0 * 2) = p0;
            *(uint32_t*)(A2l + r0 * E_SB2 + col0 * 2) = q0;
            *(uint32_t*)(A2h + r1 * E_SB2 + col0 * 2) = p1;
            *(uint32_t*)(A2l + r1 * E_SB2 + col0 * 2) = q1;
        }
        BARG(bid, 64);

        // hoist destination-index loads: latency hides under MMA2
        const int c0 = ld_idx(ei, NE + e0 + r0, eflag);
        const int c1 = ld_idx(ei, NE + e0 + r1, eflag);

        float acc2[4][4];
#pragma unroll
        for (int nc = 0; nc < 4; nc++)
#pragma unroll
            for (int j = 0; j < 4; j++) acc2[nc][j] = 0.f;
#pragma unroll
        for (int kc = 0; kc < 8; kc++) {
            const uint32_t kb = kc * 32;
            uint32_t ah0, ah1, ah2, ah3, al0, al1, al2, al3;
            ldmx4(A2hB + m0 * E_SB2 + fo2 + kb, ah0, ah1, ah2, ah3);
            ldmx4(A2lB + m0 * E_SB2 + fo2 + kb, al0, al1, al2, al3);
#pragma unroll
            for (int np = 0; np < 2; np++) {
                uint32_t bh0, bh1, bh2, bh3, bl0, bl1, bl2, bl3;
                uint32_t boff = (uint32_t)(nhf * 32 + np * 16) * E_SB2 + fo2 + kb;
                ldmx4(B2hB + boff, bh0, bh1, bh2, bh3);
                ldmx4(B2lB + boff, bl0, bl1, bl2, bl3);
                MMA3_PAIR(acc2[2 * np], acc2[2 * np + 1])
            }
        }
        BARG(bid, 64);

        const int tn = t + gridDim.x;
        const bool more = (tn < NTILE_E);
        if (more) {
            stage_xw1(tn * 128);
            stage_ea(tn * 128);
        }

        float* d0 = g_sums + (size_t)c0 * 64;
        float* d1 = g_sums + (size_t)c1 * 64;
        const bool evn = (tc & 1) == 0;
#pragma unroll
        for (int nc = 0; nc < 4; nc++) {
            int col0 = nhf * 32 + nc * 8 + 2 * tc;
            float h0 = acc2[nc][0] + b2s[col0];
            float h1 = acc2[nc][1] + b2s[col0 + 1];
            float h2 = acc2[nc][2] + b2s[col0];
            float h3 = acc2[nc][3] + b2s[col0 + 1];
            float p0 = __shfl_xor_sync(0xffffffffu, h0, 1);
            float p1 = __shfl_xor_sync(0xffffffffu, h1, 1);
            float p2 = __shfl_xor_sync(0xffffffffu, h2, 1);
            float p3 = __shfl_xor_sync(0xffffffffu, h3, 1);
            int colv = nhf * 32 + nc * 8 + 4 * (tc >> 1);
            if (evn) {
                asm volatile("red.global.add.v4.f32 [%0], {%1, %2, %3, %4};"
                             :: "l"(d0 + colv), "f"(h0), "f"(h1), "f"(p0), "f"(p1) : "memory");
            } else {
                asm volatile("red.global.add.v4.f32 [%0], {%1, %2, %3, %4};"
                             :: "l"(d1 + colv), "f"(p2), "f"(p3), "f"(h2), "f"(h3) : "memory");
            }
        }
        if (nhf == 0 && tc == 0) {
            atomicAdd(&g_cnt[c0], 1);
            atomicAdd(&g_cnt[c1], 1);
        }
        if (!more) break;
        t = tn;
    }
}

// ================= kernel 3: n1a =================
#define N1A_SB   336
#define A3_B3H   0
#define A3_B3L   86016
#define A3_AH    172032
#define A3_AL    193536
#define A3_B3S   215040
#define A3_G3S   216064
#define A3_BE3S  217088
#define A3_REDS  218112
#define A3_REDQ  219136
#define SMEM_N1A 220160

__global__ void __launch_bounds__(512, 1)
k_n1a_mma(const void* bt,
          const float* __restrict__ W3,
          const float* __restrict__ b3,
          const float* __restrict__ g3,
          const float* __restrict__ be3) {
    extern __shared__ __align__(16) char smem[];
    char* Ah = smem + A3_AH;
    char* Al = smem + A3_AL;
    char* Bh = smem + A3_B3H;
    char* Bl = smem + A3_B3L;
    float* b3s  = (float*)(smem + A3_B3S);
    float* g3s  = (float*)(smem + A3_G3S);
    float* be3s = (float*)(smem + A3_BE3S);
    float* reds = (float*)(smem + A3_REDS);
    float* redq = (float*)(smem + A3_REDQ);

    const int tid = threadIdx.x;
    const int warp = tid >> 5, lane = tid & 31;
    const int tr = lane >> 2, tc = lane & 3;
    const int grp = warp >> 2, nh = warp & 3;
    const int m0 = grp * 16;
    const int gt = tid & 127;
    const int bid = 1 + grp;
    const uint32_t sbase = smem_u32(smem);
    const uint32_t fo = frag_off(lane, N1A_SB);
    const uint32_t AhB = sbase + A3_AH, AlB = sbase + A3_AL;
    const uint32_t BhB = sbase + A3_B3H, BlB = sbase + A3_B3L;

    if (tid < 256) { b3s[tid] = b3[tid]; g3s[tid] = g3[tid]; be3s[tid] = be3[tid]; }
    for (int i = tid; i < 256 * 80; i += 512) {
        int c2 = i >> 8, n = i & 255, k0 = 2 * c2;
        float w0 = W3[(size_t)k0 * 256 + n];
        float w1 = W3[(size_t)(k0 + 1) * 256 + n];
        uint32_t p = bfpack(w0, w1);
        uint32_t q = bfpack(w0 - bflo_f(p), w1 - bfhi_f(p));
        *(uint32_t*)(Bh + n * N1A_SB + k0 * 2) = p;
        *(uint32_t*)(Bl + n * N1A_SB + k0 * 2) = q;
    }
    const int bflag = g_flags[1];
    const float4* s4 = (const float4*)g_sums;
    __syncthreads();

    auto stage = [&](int n0) {
#pragma unroll
        for (int i = gt; i < 256; i += 128) {
            int plane = i >> 7, rem = i & 127;
            int rl = rem >> 3, c16 = rem & 7;
            int node = n0 + m0 + rl; if (node >= NN) node = NN - 1;
            const __nv_bfloat16* src = (plane ? g_xl : g_xh) + (size_t)node * 64 + c16 * 8;
            uint32_t dst = (plane ? AlB : AhB) + (uint32_t)(m0 + rl) * N1A_SB + c16 * 16;
            CP16(dst, src);
        }
        {
            int plane = gt >> 6, rem = gt & 63;
            int rl = rem >> 2, c = rem & 3;
            int node = n0 + m0 + rl; if (node >= NN) node = NN - 1;
            int b = ld_idx(bt, node, bflag);
            const __nv_bfloat16* src = (plane ? g_ul : g_uh) + (size_t)b * 32 + c * 8;
            uint32_t dst = (plane ? AlB : AhB) + (uint32_t)(m0 + rl) * N1A_SB + 256 + c * 16;
            CP16(dst, src);
        }
        CP_COMMIT();
#pragma unroll
        for (int i = gt; i < 256; i += 128) {
            int rl = i >> 4, c4 = i & 15;
            int node = n0 + m0 + rl; if (node >= NN) node = NN - 1;
            float r = __frcp_rn(fmaxf((float)g_cnt[node], 1.f));
            float4 v = s4[(size_t)node * 16 + c4];
            v.x *= r; v.y *= r; v.z *= r; v.w *= r;
            uint32_t p0 = bfpack(v.x, v.y), p1 = bfpack(v.z, v.w);
            uint32_t q0 = bfpack(v.x - bflo_f(p0), v.y - bfhi_f(p0));
            uint32_t q1 = bfpack(v.z - bflo_f(p1), v.w - bfhi_f(p1));
            *(uint2*)(Ah + (m0 + rl) * N1A_SB + 128 + c4 * 8) = make_uint2(p0, p1);
            *(uint2*)(Al + (m0 + rl) * N1A_SB + 128 + c4 * 8) = make_uint2(q0, q1);
        }
    };

    int t = blockIdx.x;
    stage(t * 64);

    for (;;) {
        const int n0 = t * 64;
        CP_WAIT0();
        BARG(bid, 128);

        float acc[8][4];
#pragma unroll
        for (int nc = 0; nc < 8; nc++)
#pragma unroll
            for (int j = 0; j < 4; j++) acc[nc][j] = 0.f;
#pragma unroll
        for (int kc = 0; kc < 10; kc++) {
            const uint32_t kb = kc * 32;
            uint32_t ah0, ah1, ah2, ah3, al0, al1, al2, al3;
            ldmx4(AhB + m0 * N1A_SB + fo + kb, ah0, ah1, ah2, ah3);
            ldmx4(AlB + m0 * N1A_SB + fo + kb, al0, al1, al2, al3);
#pragma unroll
            for (int np = 0; np < 4; np++) {
                uint32_t bh0, bh1, bh2, bh3, bl0, bl1, bl2, bl3;
                uint32_t boff = (uint32_t)(nh * 64 + np * 16) * N1A_SB + fo + kb;
                ldmx4(BhB + boff, bh0, bh1, bh2, bh3);
                ldmx4(BlB + boff, bl0, bl1, bl2, bl3);
                MMA3_PAIR(acc[2 * np], acc[2 * np + 1])
            }
        }

        float s0 = 0.f, q0s = 0.f, s1 = 0.f, q1s = 0.f;
#pragma unroll
        for (int nc = 0; nc < 8; nc++) {
            int col0 = nh * 64 + nc * 8 + 2 * tc;
            float v0 = acc[nc][0] + b3s[col0];
            float v1 = acc[nc][1] + b3s[col0 + 1];
            float v2 = acc[nc][2] + b3s[col0];
            float v3 = acc[nc][3] + b3s[col0 + 1];
            acc[nc][0] = v0; acc[nc][1] = v1; acc[nc][2] = v2; acc[nc][3] = v3;
            s0 += v0 + v1; q0s = fmaf(v0, v0, fmaf(v1, v1, q0s));
            s1 += v2 + v3; q1s = fmaf(v2, v2, fmaf(v3, v3, q1s));
        }
#pragma unroll
        for (int o = 1; o <= 2; o <<= 1) {
            s0  += __shfl_xor_sync(0xffffffffu, s0, o);
            q0s += __shfl_xor_sync(0xffffffffu, q0s, o);
            s1  += __shfl_xor_sync(0xffffffffu, s1, o);
            q1s += __shfl_xor_sync(0xffffffffu, q1s, o);
        }
        const int r0 = m0 + tr, r1 = r0 + 8;
        if (tc == 0) {
            reds[nh * 64 + r0] = s0; redq[nh * 64 + r0] = q0s;
            reds[nh * 64 + r1] = s1; redq[nh * 64 + r1] = q1s;
        }
        BARG(bid, 128);

        const int tn = t + gridDim.x;
        const bool more = (tn < NTILE_N);
        if (more) stage(tn * 64);

        float ts0 = reds[r0] + reds[64 + r0] + reds[128 + r0] + reds[192 + r0];
        float tq0 = redq[r0] + redq[64 + r0] + redq[128 + r0] + redq[192 + r0];
        float ts1 = reds[r1] + reds[64 + r1] + reds[128 + r1] + reds[192 + r1];
        float tq1 = redq[r1] + redq[64 + r1] + redq[128 + r1] + redq[192 + r1];
        float mean0 = ts0 * (1.f / 256.f);
        float rstd0 = rsqrtf(tq0 * (1.f / 256.f) - mean0 * mean0 + 1e-5f);
        float mean1 = ts1 * (1.f / 256.f);
        float rstd1 = rsqrtf(tq1 * (1.f / 256.f) - mean1 * mean1 + 1e-5f);

        const int node0 = n0 + r0, node1 = n0 + r1;
#pragma unroll
        for (int nc = 0; nc < 8; nc++) {
            int col0 = nh * 64 + nc * 8 + 2 * tc;
            float w0 = fmaxf((acc[nc][0] - mean0) * rstd0 * g3s[col0]     + be3s[col0],     0.f);
            float w1 = fmaxf((acc[nc][1] - mean0) * rstd0 * g3s[col0 + 1] + be3s[col0 + 1], 0.f);
            float w2 = fmaxf((acc[nc][2] - mean1) * rstd1 * g3s[col0]     + be3s[col0],     0.f);
            float w3 = fmaxf((acc[nc][3] - mean1) * rstd1 * g3s[col0 + 1] + be3s[col0 + 1], 0.f);
            if (node0 < NN) {
                uint32_t p = bfpack(w0, w1);
                uint32_t q = bfpack(w0 - bflo_f(p), w1 - bfhi_f(p));
                *(uint32_t*)&g_a3h[(size_t)node0 * 256 + col0] = p;
                *(uint32_t*)&g_a3l[(size_t)node0 * 256 + col0] = q;
            }
            if (node1 < NN) {
                uint32_t p = bfpack(w2, w3);
                uint32_t q = bfpack(w2 - bflo_f(p), w3 - bfhi_f(p));
                *(uint32_t*)&g_a3h[(size_t)node1 * 256 + col0] = p;
                *(uint32_t*)&g_a3l[(size_t)node1 * 256 + col0] = q;
            }
        }
        if (!more) break;
        t = tn;
    }
}

// ================= kernel 4: n1b =================
#define N1B_SB   528
#define A4_B4H   0
#define A4_B4L   67584
#define A4_AH    135168
#define A4_AL    168960
#define A4_B4S   202752
#define A4_G4S   203264
#define A4_BE4S  203776
#define A4_REDS  204288
#define A4_REDQ  205312
#define SMEM_N1B 206336

__global__ void __launch_bounds__(512, 1)
k_n1b_mma(const float* __restrict__ W4,
          const float* __restrict__ b4,
          const float* __restrict__ g4,
          const float* __restrict__ be4) {
    extern __shared__ __align__(16) char smem[];
    char* Bh = smem + A4_B4H;
    char* Bl = smem + A4_B4L;
    float* b4s  = (float*)(smem + A4_B4S);
    float* g4s  = (float*)(smem + A4_G4S);
    float* be4s = (float*)(smem + A4_BE4S);
    float* reds = (float*)(smem + A4_REDS);
    float* redq = (float*)(smem + A4_REDQ);

    const int tid = threadIdx.x;
    const int warp = tid >> 5, lane = tid & 31;
    const int tr = lane >> 2, tc = lane & 3;
    const int grp = warp >> 2, nh = warp & 3;
    const int m0 = grp * 16;
    const int gt = tid & 127;
    const int bid = 1 + grp;
    const uint32_t sbase = smem_u32(smem);
    const uint32_t fo = frag_off(lane, N1B_SB);
    const uint32_t AhB = sbase + A4_AH, AlB = sbase + A4_AL;
    const uint32_t BhB = sbase + A4_B4H, BlB = sbase + A4_B4L;

    if (tid < 128) { b4s[tid] = b4[tid]; g4s[tid] = g4[tid]; be4s[tid] = be4[tid]; }
    for (int i = tid; i < 128 * 128; i += 512) {
        int c2 = i >> 7, n = i & 127, k0 = 2 * c2;
        float w0 = W4[(size_t)k0 * 128 + n];
        float w1 = W4[(size_t)(k0 + 1) * 128 + n];
        uint32_t p = bfpack(w0, w1);
        uint32_t q = bfpack(w0 - bflo_f(p), w1 - bfhi_f(p));
        *(uint32_t*)(Bh + n * N1B_SB + k0 * 2) = p;
        *(uint32_t*)(Bl + n * N1B_SB + k0 * 2) = q;
    }
    __syncthreads();

    auto stage = [&](int n0) {
#pragma unroll
        for (int i = gt; i < 1024; i += 128) {
            int plane = i >> 9, rem = i & 511;
            int rl = rem >> 5, c16 = rem & 31;
            int node = n0 + m0 + rl; if (node >= NN) node = NN - 1;
            const __nv_bfloat16* src = (plane ? g_a3l : g_a3h) + (size_t)node * 256 + c16 * 8;
            uint32_t dst = (plane ? AlB : AhB) + (uint32_t)(m0 + rl) * N1B_SB + c16 * 16;
            CP16(dst, src);
        }
        CP_COMMIT();
    };

    int t = blockIdx.x;
    stage(t * 64);

    for (;;) {
        const int n0 = t * 64;
        CP_WAIT0();
        BARG(bid, 128);

        float acc[4][4];
#pragma unroll
        for (int nc = 0; nc < 4; nc++)
#pragma unroll
            for (int j = 0; j < 4; j++) acc[nc][j] = 0.f;
#pragma unroll
        for (int kc = 0; kc < 16; kc++) {
            const uint32_t kb = kc * 32;
            uint32_t ah0, ah1, ah2, ah3, al0, al1, al2, al3;
            ldmx4(AhB + m0 * N1B_SB + fo + kb, ah0, ah1, ah2, ah3);
            ldmx4(AlB + m0 * N1B_SB + fo + kb, al0, al1, al2, al3);
#pragma unroll
            for (int np = 0; np < 2; np++) {
                uint32_t bh0, bh1, bh2, bh3, bl0, bl1, bl2, bl3;
                uint32_t boff = (uint32_t)(nh * 32 + np * 16) * N1B_SB + fo + kb;
                ldmx4(BhB + boff, bh0, bh1, bh2, bh3);
                ldmx4(BlB + boff, bl0, bl1, bl2, bl3);
                MMA3_PAIR(acc[2 * np], acc[2 * np + 1])
            }
        }

        float s0 = 0.f, q0s = 0.f, s1 = 0.f, q1s = 0.f;
#pragma unroll
        for (int nc = 0; nc < 4; nc++) {
            int col0 = nh * 32 + nc * 8 + 2 * tc;
            float v0 = acc[nc][0] + b4s[col0];
            float v1 = acc[nc][1] + b4s[col0 + 1];
            float v2 = acc[nc][2] + b4s[col0];
            float v3 = acc[nc][3] + b4s[col0 + 1];
            acc[nc][0] = v0; acc[nc][1] = v1; acc[nc][2] = v2; acc[nc][3] = v3;
            s0 += v0 + v1; q0s = fmaf(v0, v0, fmaf(v1, v1, q0s));
            s1 += v2 + v3; q1s = fmaf(v2, v2, fmaf(v3, v3, q1s));
        }
#pragma unroll
        for (int o = 1; o <= 2; o <<= 1) {
            s0  += __shfl_xor_sync(0xffffffffu, s0, o);
            q0s += __shfl_xor_sync(0xffffffffu, q0s, o);
            s1  += __shfl_xor_sync(0xffffffffu, s1, o);
            q1s += __shfl_xor_sync(0xffffffffu, q1s, o);
        }
        const int r0 = m0 + tr, r1 = r0 + 8;
        if (tc == 0) {
            reds[nh * 64 + r0] = s0; redq[nh * 64 + r0] = q0s;
            reds[nh * 64 + r1] = s1; redq[nh * 64 + r1] = q1s;
        }
        BARG(bid, 128);

        const int tn = t + gridDim.x;
        const bool more = (tn < NTILE_N);
        if (more) stage(tn * 64);

        float ts0 = reds[r0] + reds[64 + r0] + reds[128 + r0] + reds[192 + r0];
        float tq0 = redq[r0] + redq[64 + r0] + redq[128 + r0] + redq[192 + r0];
        float ts1 = reds[r1] + reds[64 + r1] + reds[128 + r1] + reds[192 + r1];
        float tq1 = redq[r1] + redq[64 + r1] + redq[128 + r1] + redq[192 + r1];
        float mean0 = ts0 * (1.f / 128.f);
        float rstd0 = rsqrtf(tq0 * (1.f / 128.f) - mean0 * mean0 + 1e-5f);
        float mean1 = ts1 * (1.f / 128.f);
        float rstd1 = rsqrtf(tq1 * (1.f / 128.f) - mean1 * mean1 + 1e-5f);

        const int node0 = n0 + r0, node1 = n0 + r1;
#pragma unroll
        for (int nc = 0; nc < 4; nc++) {
            int col0 = nh * 32 + nc * 8 + 2 * tc;
            float w0 = fmaxf((acc[nc][0] - mean0) * rstd0 * g4s[col0]     + be4s[col0],     0.f);
            float w1 = fmaxf((acc[nc][1] - mean0) * rstd0 * g4s[col0 + 1] + be4s[col0 + 1], 0.f);
            float w2 = fmaxf((acc[nc][2] - mean1) * rstd1 * g4s[col0]     + be4s[col0],     0.f);
            float w3 = fmaxf((acc[nc][3] - mean1) * rstd1 * g4s[col0 + 1] + be4s[col0 + 1], 0.f);
            if (node0 < NN) {
                uint32_t p = bfpack(w0, w1);
                uint32_t q = bfpack(w0 - bflo_f(p), w1 - bfhi_f(p));
                *(uint32_t*)&g_a4h[(size_t)node0 * 128 + col0] = p;
                *(uint32_t*)&g_a4l[(size_t)node0 * 128 + col0] = q;
            }
            if (node1 < NN) {
                uint32_t p = bfpack(w2, w3);
                uint32_t q = bfpack(w2 - bflo_f(p), w3 - bfhi_f(p));
                *(uint32_t*)&g_a4h[(size_t)node1 * 128 + col0] = p;
                *(uint32_t*)&g_a4l[(size_t)node1 * 128 + col0] = q;
            }
        }
        if (!more) break;
        t = tn;
    }
}

// ================= kernel 5: n2 =================
#define N2_SB    272
#define Z_SB     80
#define N2_BH    0
#define N2_BL    17408
#define N2_AH    34816
#define N2_AL    69632
#define N2_ZH    104448
#define N2_ZL    114688
#define N2_XH    124928
#define N2_XL    130048
#define N2_MUV   135168
#define N2_BM    169984
#define N2_BV    170112
#define N2_BX    170240
#define SMEM_N2  170496

__global__ void __launch_bounds__(512, 1)
k_n2_mma(const float* __restrict__ Wm, const float* __restrict__ bm,
         const float* __restrict__ Wv, const float* __restrict__ bv,
         const float* __restrict__ Wx, const float* __restrict__ bx,
         float* __restrict__ out) {
    extern __shared__ __align__(16) char smem[];
    char* Bh = smem + N2_BH;
    char* Bl = smem + N2_BL;
    char* Zh = smem + N2_ZH;
    char* Zl = smem + N2_ZL;
    char* Xh = smem + N2_XH;
    char* Xl = smem + N2_XL;
    float* muv = (float*)(smem + N2_MUV);
    float* bms = (float*)(smem + N2_BM);
    float* bvs = (float*)(smem + N2_BV);
    float* bxs = (float*)(smem + N2_BX);

    const int tid = threadIdx.x;
    const int warp = tid >> 5, lane = tid & 31;
    const int tr = lane >> 2, tc = lane & 3;
    const int mq = warp >> 1, nhf = warp & 1;
    const int m0 = mq * 16;
    const int gt = tid & 63;
    const int bid = 1 + mq;
    const uint32_t sbase = smem_u32(smem);
    const uint32_t foA = frag_off(lane, N2_SB);
    const uint32_t foZ = frag_off(lane, Z_SB);
    const uint32_t AhB = sbase + N2_AH, AlB = sbase + N2_AL;
    const uint32_t BhB = sbase + N2_BH, BlB = sbase + N2_BL;
    const uint32_t ZhB = sbase + N2_ZH, ZlB = sbase + N2_ZL;
    const uint32_t XhB = sbase + N2_XH, XlB = sbase + N2_XL;

    if (tid < 32) { bms[tid] = bm[tid]; bvs[tid] = bv[tid]; }
    if (tid < 64) bxs[tid] = bx[tid];
    for (int i = tid; i < 64 * 64; i += 512) {
        int c2 = i >> 6, j = i & 63, k0 = 2 * c2;
        float w0, w1;
        if (j < 32) { w0 = Wm[(size_t)k0 * 32 + j]; w1 = Wm[(size_t)(k0 + 1) * 32 + j]; }
        else        { w0 = Wv[(size_t)k0 * 32 + j - 32]; w1 = Wv[(size_t)(k0 + 1) * 32 + j - 32]; }
        uint32_t p = bfpack(w0, w1);
        uint32_t q = bfpack(w0 - bflo_f(p), w1 - bfhi_f(p));
        *(uint32_t*)(Bh + j * N2_SB + k0 * 2) = p;
        *(uint32_t*)(Bl + j * N2_SB + k0 * 2) = q;
    }
    for (int i = tid; i < 64 * 16; i += 512) {
        int c2 = i >> 6, j = i & 63, k0 = 2 * c2;
        float w0 = Wx[(size_t)k0 * 64 + j];
        float w1 = Wx[(size_t)(k0 + 1) * 64 + j];
        uint32_t p = bfpack(w0, w1);
        uint32_t q = bfpack(w0 - bflo_f(p), w1 - bfhi_f(p));
        *(uint32_t*)(Xh + j * Z_SB + k0 * 2) = p;
        *(uint32_t*)(Xl + j * Z_SB + k0 * 2) = q;
    }
    __syncthreads();

    auto stage = [&](int n0) {
#pragma unroll
        for (int i = gt; i < 512; i += 64) {
            int plane = i >> 8, rem = i & 255;
            int rl = rem >> 4, c16 = rem & 15;
            int node = n0 + m0 + rl; if (node >= NN) node = NN - 1;
            const __nv_bfloat16* src = (plane ? g_a4l : g_a4h) + (size_t)node * 128 + c16 * 8;
            uint32_t dst = (plane ? AlB : AhB) + (uint32_t)(m0 + rl) * N2_SB + c16 * 16;
            CP16(dst, src);
        }
        CP_COMMIT();
    };

    int t = blockIdx.x;
    stage(t * 128);

    for (;;) {
        const int n0 = t * 128;
        CP_WAIT0();
        BARG(bid, 64);

        float acc[4][4];
#pragma unroll
        for (int nc = 0; nc < 4; nc++)
#pragma unroll
            for (int j = 0; j < 4; j++) acc[nc][j] = 0.f;
#pragma unroll
        for (int kc = 0; kc < 8; kc++) {
            const uint32_t kb = kc * 32;
            uint32_t ah0, ah1, ah2, ah3, al0, al1, al2, al3;
            ldmx4(AhB + m0 * N2_SB + foA + kb, ah0, ah1, ah2, ah3);
            ldmx4(AlB + m0 * N2_SB + foA + kb, al0, al1, al2, al3);
#pragma unroll
            for (int np = 0; np < 2; np++) {
                uint32_t bh0, bh1, bh2, bh3, bl0, bl1, bl2, bl3;
                uint32_t boff = (uint32_t)(nhf * 32 + np * 16) * N2_SB + foA + kb;
                ldmx4(BhB + boff, bh0, bh1, bh2, bh3);
                ldmx4(BlB + boff, bl0, bl1, bl2, bl3);
                MMA3_PAIR(acc[2 * np], acc[2 * np + 1])
            }
        }

        const int r0 = m0 + tr, r1 = r0 + 8;
#pragma unroll
        for (int nc = 0; nc < 4; nc++) {
            int col0 = nhf * 32 + nc * 8 + 2 * tc;
            float bb0 = (nhf == 0) ? bms[col0]     : bvs[col0 - 32];
            float bb1 = (nhf == 0) ? bms[col0 + 1] : bvs[col0 - 31];
            int so = (nhf == 0) ? col0 : col0 + 2;
            muv[r0 * 68 + so]     = acc[nc][0] + bb0;
            muv[r0 * 68 + so + 1] = acc[nc][1] + bb1;
            muv[r1 * 68 + so]     = acc[nc][2] + bb0;
            muv[r1 * 68 + so + 1] = acc[nc][3] + bb1;
        }
        BARG(bid, 64);

        const int tn = t + gridDim.x;
        const bool more = (tn < NTILE_N2);
        if (more) stage(tn * 128);

#pragma unroll
        for (int it = 0; it < 8; it++) {
            int idx = it * 64 + gt;
            int rl = idx >> 5, col = idx & 31;
            int row = m0 + rl, node = n0 + row;
            float mu = muv[row * 68 + col];
            float lv = muv[row * 68 + 34 + col];
            float z = mu + jax_normal_eps((unsigned)(node * 32 + col)) * expf(0.5f * lv);
            __nv_bfloat16 zh = __float2bfloat16_rn(z);
            *(__nv_bfloat16*)(Zh + row * Z_SB + col * 2) = zh;
            *(__nv_bfloat16*)(Zl + row * Z_SB + col * 2) =
                __float2bfloat16_rn(z - __bfloat162float(zh));
            if (node < NN) {
                out[(size_t)NN * 64 + (size_t)node * 32 + col] = mu;
                out[(size_t)NN * 96 + (size_t)node * 32 + col] = lv;
            }
        }
        BARG(bid, 64);

        float acc2[4][4];
#pragma unroll
        for (int nc = 0; nc < 4; nc++)
#pragma unroll
            for (int j = 0; j < 4; j++) acc2[nc][j] = 0.f;
#pragma unroll
        for (int kc = 0; kc < 2; kc++) {
            const uint32_t kb = kc * 32;
            uint32_t ah0, ah1, ah2, ah3, al0, al1, al2, al3;
            ldmx4(ZhB + m0 * Z_SB + foZ + kb, ah0, ah1, ah2, ah3);
            ldmx4(ZlB + m0 * Z_SB + foZ + kb, al0, al1, al2, al3);
#pragma unroll
            for (int np = 0; np < 2; np++) {
                uint32_t bh0, bh1, bh2, bh3, bl0, bl1, bl2, bl3;
                uint32_t boff = (uint32_t)(nhf * 32 + np * 16) * Z_SB + foZ + kb;
                ldmx4(XhB + boff, bh0, bh1, bh2, bh3);
                ldmx4(XlB + boff, bl0, bl1, bl2, bl3);
                MMA3_PAIR(acc2[2 * np], acc2[2 * np + 1])
            }
        }
        const int node0 = n0 + r0, node1 = n0 + r1;
#pragma unroll
        for (int nc = 0; nc < 4; nc++) {
            int col0 = nhf * 32 + nc * 8 + 2 * tc;
            if (node0 < NN)
                *(float2*)&out[(size_t)node0 * 64 + col0] =
                    make_float2(acc2[nc][0] + bxs[col0], acc2[nc][1] + bxs[col0 + 1]);
            if (node1 < NN)
                *(float2*)&out[(size_t)node1 * 64 + col0] =
                    make_float2(acc2[nc][2] + bxs[col0], acc2[nc][3] + bxs[col0 + 1]);
        }
        if (!more) break;
        t = tn;
    }
}

// ---------------- launch ----------------
extern "C" void kernel_launch(void* const* d_in, const int* in_sizes, int n_in,
                              void* d_out, int out_size) {
    const float* x  = (const float*)d_in[0];
    const void*  ei = d_in[1];
    const float* ea = (const float*)d_in[2];
    const float* u  = (const float*)d_in[3];
    const void*  bt = d_in[4];
    const float* W1 = (const float*)d_in[6];  const float* b1  = (const float*)d_in[7];
    const float* g1 = (const float*)d_in[8];  const float* be1 = (const float*)d_in[9];
    const float* W2 = (const float*)d_in[10]; const float* b2  = (const float*)d_in[11];
    const float* W3 = (const float*)d_in[12]; const float* b3  = (const float*)d_in[13];
    const float* g3 = (const float*)d_in[14]; const float* be3 = (const float*)d_in[15];
    const float* W4 = (const float*)d_in[16]; const float* b4  = (const float*)d_in[17];
    const float* g4 = (const float*)d_in[18]; const float* be4 = (const float*)d_in[19];
    const float* Wm = (const float*)d_in[20]; const float* bm  = (const float*)d_in[21];
    const float* Wv = (const float*)d_in[22]; const float* bv  = (const float*)d_in[23];
    const float* Wx = (const float*)d_in[24]; const float* bx  = (const float*)d_in[25];
    float* out = (float*)d_out;

    cudaFuncSetAttribute(k_xw1, cudaFuncAttributeMaxDynamicSharedMemorySize, SMEM_XW);
    cudaFuncSetAttribute(k_edge_mma, cudaFuncAttributeMaxDynamicSharedMemorySize, SMEM_EDGE);
    cudaFuncSetAttribute(k_n1a_mma, cudaFuncAttributeMaxDynamicSharedMemorySize, SMEM_N1A);
    cudaFuncSetAttribute(k_n1b_mma, cudaFuncAttributeMaxDynamicSharedMemorySize, SMEM_N1B);
    cudaFuncSetAttribute(k_n2_mma,  cudaFuncAttributeMaxDynamicSharedMemorySize, SMEM_N2);

    k_init<<<592, 256>>>((const int*)ei, (const int*)bt, x, u);
    k_xw1<<<148, 512, SMEM_XW>>>(W1);
    k_edge_mma<<<148, 512, SMEM_EDGE>>>(ei, ea, W1, b1, g1, be1, W2, b2);
    k_n1a_mma<<<148, 512, SMEM_N1A>>>(bt, W3, b3, g3, be3);
    k_n1b_mma<<<148, 512, SMEM_N1B>>>(W4, b4, g4, be4);
    k_n2_mma<<<148, 512, SMEM_N2>>>(Wm, bm, Wv, bv, Wx, bx, out);
}